// round 6
// baseline (speedup 1.0000x reference)
#include <cuda_runtime.h>
#include <cuda_fp16.h>
#include <cstdint>
#include <math.h>

#define S_LEN 4096
#define E_DIM 1024
#define D_DIM 1024

typedef __half h16;

// ---------------- scratch (device globals; no allocation allowed) ----------
__device__ h16   g_xh[(size_t)S_LEN * E_DIM];
__device__ h16   g_xl[(size_t)S_LEN * E_DIM];
__device__ h16   g_Wth[3][(size_t)D_DIM * E_DIM];   // W^T hi (stacked q,k,v)
__device__ h16   g_Wtl[3][(size_t)D_DIM * E_DIM];   // W^T lo (v slot unused)
__device__ h16   g_Qh[(size_t)S_LEN * D_DIM];
__device__ h16   g_Ql[(size_t)S_LEN * D_DIM];
__device__ h16   g_Kh[(size_t)S_LEN * D_DIM];
__device__ h16   g_Kl[(size_t)S_LEN * D_DIM];
__device__ float g_Vf[(size_t)S_LEN * D_DIM];
__device__ h16   g_Vth[(size_t)D_DIM * S_LEN];      // V^T fp16 (single)
__device__ float g_Pf[(size_t)S_LEN * S_LEN];       // raw scores (lower tri)
__device__ h16   g_Ph[(size_t)S_LEN * S_LEN];       // probs fp16 (single)

// ---------------- PTX helpers (sm_80-compatible only) -----------------------
__device__ __forceinline__ uint32_t smem_u32(const void* p) {
    uint32_t a;
    asm("{ .reg .u64 t; cvta.to.shared.u64 t, %1; cvt.u32.u64 %0, t; }" : "=r"(a) : "l"(p));
    return a;
}

#define CP_ASYNC16(saddr, gaddr) \
    asm volatile("cp.async.cg.shared.global [%0], [%1], 16;" \
                 :: "r"(saddr), "l"(gaddr) : "memory")
#define CP_COMMIT() asm volatile("cp.async.commit_group;" ::: "memory")
#define CP_WAIT(N)  asm volatile("cp.async.wait_group %0;" :: "n"(N) : "memory")

#define LDSM4(r0, r1, r2, r3, addr) \
    asm volatile("ldmatrix.sync.aligned.m8n8.x4.shared.b16 {%0,%1,%2,%3}, [%4];" \
                 : "=r"(r0), "=r"(r1), "=r"(r2), "=r"(r3) : "r"(addr))

#define MMA16816(c0, c1, c2, c3, a0, a1, a2, a3, b0, b1) \
    asm volatile("mma.sync.aligned.m16n8k16.row.col.f32.f16.f16.f32 " \
                 "{%0,%1,%2,%3}, {%4,%5,%6,%7}, {%8,%9}, {%0,%1,%2,%3};" \
                 : "+f"(c0), "+f"(c1), "+f"(c2), "+f"(c3) \
                 : "r"(a0), "r"(a1), "r"(a2), "r"(a3), "r"(b0), "r"(b1))

// ---------------- aux kernels -----------------------------------------------
__global__ __launch_bounds__(256)
void split_f32(const float* __restrict__ src, h16* __restrict__ h,
               h16* __restrict__ l, int n)
{
    for (int i = blockIdx.x * 256 + threadIdx.x; i < n; i += gridDim.x * 256) {
        float v = src[i];
        h16 a = __float2half_rn(v);
        h[i] = a;
        l[i] = __float2half_rn(v - __half2float(a));
    }
}

// All three weight transposes in one launch (z selects); z==2 (Wv) skips lo.
__global__ __launch_bounds__(256)
void transpose_split_w(const float* __restrict__ Wq, const float* __restrict__ Wk,
                       const float* __restrict__ Wv,
                       h16* __restrict__ dh, h16* __restrict__ dl)
{
    const int z = blockIdx.z;
    const float* src = (z == 0) ? Wq : (z == 1) ? Wk : Wv;
    const size_t WSZ = (size_t)D_DIM * E_DIM;
    h16* dhp = dh + (size_t)z * WSZ;
    h16* dlp = dl + (size_t)z * WSZ;

    __shared__ float t[32][33];
    const int bx = blockIdx.x * 32;  // col of src (D)
    const int by = blockIdx.y * 32;  // row of src (E)
    const int tx = threadIdx.x & 31, ty = threadIdx.x >> 5;
#pragma unroll
    for (int j = ty; j < 32; j += 8)
        t[j][tx] = src[(size_t)(by + j) * D_DIM + bx + tx];
    __syncthreads();
#pragma unroll
    for (int j = ty; j < 32; j += 8) {
        float v = t[tx][j];
        size_t o = (size_t)(bx + j) * E_DIM + by + tx;
        h16 a = __float2half_rn(v);
        dhp[o] = a;
        if (z < 2) dlp[o] = __float2half_rn(v - __half2float(a));
    }
}

// V transpose (fp16 single): dst[c][r] = h(src[r][c])
__global__ __launch_bounds__(256)
void transpose_half(const float* __restrict__ src, h16* __restrict__ dh,
                    int R, int C)
{
    __shared__ float t[32][33];
    const int bx = blockIdx.x * 32;
    const int by = blockIdx.y * 32;
    const int tx = threadIdx.x & 31, ty = threadIdx.x >> 5;
#pragma unroll
    for (int j = ty; j < 32; j += 8)
        t[j][tx] = src[(size_t)(by + j) * C + bx + tx];
    __syncthreads();
#pragma unroll
    for (int j = ty; j < 32; j += 8)
        dh[(size_t)(bx + j) * R + by + tx] = __float2half_rn(t[tx][j]);
}

// causal softmax over raw scores Pf; writes fp16 probs, zero-padded to the
// 128-aligned block boundary (= kEnd consumed by the PV GEMM).
__global__ __launch_bounds__(256)
void softmax_half(float* __restrict__ Pf, h16* __restrict__ Ph)
{
    const int row = blockIdx.x;
    float* p = Pf + (size_t)row * S_LEN;
    h16* ph = Ph + (size_t)row * S_LEN;
    const int len = row + 1;
    const int tid = threadIdx.x, lane = tid & 31, warp = tid >> 5;
    __shared__ float red[8];
    __shared__ float bcast;

    float m = -3.4e38f;
    for (int j = tid; j < len; j += 256) m = fmaxf(m, p[j]);
#pragma unroll
    for (int o = 16; o; o >>= 1) m = fmaxf(m, __shfl_xor_sync(0xffffffffu, m, o));
    if (lane == 0) red[warp] = m;
    __syncthreads();
    if (tid == 0) {
        float v = red[0];
#pragma unroll
        for (int i = 1; i < 8; i++) v = fmaxf(v, red[i]);
        bcast = v;
    }
    __syncthreads();
    m = bcast;
    __syncthreads();

    float s = 0.0f;
    for (int j = tid; j < len; j += 256) {
        float e = expf(p[j] - m);
        p[j] = e;
        s += e;
    }
#pragma unroll
    for (int o = 16; o; o >>= 1) s += __shfl_xor_sync(0xffffffffu, s, o);
    if (lane == 0) red[warp] = s;
    __syncthreads();
    if (tid == 0) {
        float v = 0.0f;
#pragma unroll
        for (int i = 0; i < 8; i++) v += red[i];
        bcast = 1.0f / v;
    }
    __syncthreads();
    const float inv = bcast;

    for (int j = tid; j < len; j += 256)
        ph[j] = __float2half_rn(p[j] * inv);
    const int kpad = ((row >> 7) + 1) << 7;
    const h16 z = __float2half_rn(0.0f);
    for (int j = len + tid; j < kpad; j += 256) ph[j] = z;
}

// ---------------- split-fp16 GEMM via mma.sync (runtime nprod) ---------------
// nprod=3: C = scale*(AhBh + AhBl + AlBh)   nprod=1: C = scale*AhBh
// mode 0: fused QKV. grid=768: t<256 -> Q (3p, split out), t<512 -> K (3p,
//         split out), t>=512 -> V (1-product, fp32 out). Heavy tiles first.
// mode 1: triangular 1D grid (scores), fp32 out Cf.
// mode 2: causal PV, kEnd=(br+1)*128, heavy-first zigzag remap, fp32 out Cf.
#define RSB     80                   // smem row stride bytes (64B data + 16B pad)
#define TILE_B  (128 * RSB)          // 10240
#define SMEM3   (2 * 4 * TILE_B + 128)   // 82048
#define SMEM1   (2 * 2 * TILE_B + 128)   // 41088

__global__ __launch_bounds__(256, 2)
void mm_gemm(const h16* __restrict__ Ah, const h16* __restrict__ Al,
             const h16* __restrict__ Bh, const h16* __restrict__ Bl,
             float* __restrict__ Cf, h16* __restrict__ Ch, h16* __restrict__ Cl,
             h16* __restrict__ Kh2, h16* __restrict__ Kl2,
             int Ktot, int ldc, float scale, int mode, int nprod)
{
    extern __shared__ char smem[];
    const int tid = threadIdx.x;
    const int wid = tid >> 5;
    const int lane = tid & 31;
    const int wm = wid >> 2;          // 0..1  (64-row slabs)
    const int wn = wid & 3;           // 0..3  (32-col slabs)

    int br, bc, p = 0;
    if (mode == 1) {
        int t = blockIdx.x;
        br = (int)((sqrtf(8.0f * (float)t + 1.0f) - 1.0f) * 0.5f);
        while ((br + 1) * (br + 2) / 2 <= t) br++;
        while (br * (br + 1) / 2 > t) br--;
        bc = t - br * (br + 1) / 2;
    } else if (mode == 2) {
        int t = blockIdx.x;
        int r = (t < 148) ? t : (403 - t);
        br = 31 - (r >> 3);
        bc = r & 7;
    } else {
        int t = blockIdx.x;
        p = t >> 8;
        int r = t & 255;
        br = r >> 3;
        bc = r & 7;
        if (p == 2) nprod = 1;        // V projection: single product
    }
    const int m0 = br * 128, n0 = bc * 128;
    const int kEnd = (mode == 2) ? (br + 1) * 128 : Ktot;
    const int NC = kEnd / 32;

    const int ntiles = (nprod == 3) ? 4 : 2;
    const uint32_t stage_b = (uint32_t)ntiles * TILE_B;

    const h16* Bhp = Bh + (size_t)p * ((size_t)D_DIM * E_DIM);
    const h16* Blp = Bl + (size_t)p * ((size_t)D_DIM * E_DIM);

    const uint32_t tiles = (smem_u32(smem) + 127u) & ~127u;

    float acc[4][4][4];
#pragma unroll
    for (int i = 0; i < 4; i++)
#pragma unroll
        for (int j = 0; j < 4; j++)
#pragma unroll
            for (int k = 0; k < 4; k++) acc[i][j][k] = 0.0f;

    auto load_stage = [&](int c) {
        const uint32_t st = tiles + (uint32_t)(c & 1) * stage_b;
        const int k0 = c * 32;
        const h16* srcs[4];
        if (nprod == 3) {
            srcs[0] = Ah  + (size_t)m0 * Ktot + k0;
            srcs[1] = Al  + (size_t)m0 * Ktot + k0;
            srcs[2] = Bhp + (size_t)n0 * Ktot + k0;
            srcs[3] = Blp + (size_t)n0 * Ktot + k0;
        } else {
            srcs[0] = Ah  + (size_t)m0 * Ktot + k0;
            srcs[1] = Bhp + (size_t)n0 * Ktot + k0;
        }
        for (int t = 0; t < ntiles; t++) {
#pragma unroll
            for (int j2 = 0; j2 < 2; j2++) {
                int j = tid + j2 * 256;          // 0..511
                int row = j >> 2, ck = j & 3;
                const void* g = srcs[t] + (size_t)row * Ktot + ck * 8;
                uint32_t s = st + (uint32_t)t * TILE_B + row * RSB + ck * 16;
                CP_ASYNC16(s, g);
            }
        }
        CP_COMMIT();
    };

    load_stage(0);

    const int lr15 = lane & 15;
    const int lhi16 = (lane >> 4) * 16;          // A chunk-half byte offset
    const int l7 = lane & 7;
    const int bmat = lane >> 3;                  // 0..3
    const int bnsub = (bmat >> 1) * 8;
    const int bkb = (bmat & 1) * 16;

    for (int c = 0; c < NC; c++) {
        if (c + 1 < NC) { load_stage(c + 1); CP_WAIT(1); }
        else            { CP_WAIT(0); }
        __syncthreads();

        const uint32_t st = tiles + (uint32_t)(c & 1) * stage_b;
        const uint32_t aHb = st + (uint32_t)(wm * 64) * RSB;
        const uint32_t aLb = aHb + TILE_B;                       // nprod==3 only
        const uint32_t bHb = st + (uint32_t)(ntiles / 2) * TILE_B
                                + (uint32_t)(wn * 32) * RSB;
        const uint32_t bLb = bHb + TILE_B;                       // nprod==3 only

#pragma unroll
        for (int ks = 0; ks < 2; ks++) {
            const uint32_t akb  = (uint32_t)(ks * 32 + lhi16);
            const uint32_t bkb2 = (uint32_t)(ks * 32) + bkb;

            uint32_t ah[4][4], al[4][4], bh[2][4], bl[2][4];
#pragma unroll
            for (int mi = 0; mi < 4; mi++) {
                uint32_t ra = (uint32_t)(mi * 16 + lr15) * RSB + akb;
                LDSM4(ah[mi][0], ah[mi][1], ah[mi][2], ah[mi][3], aHb + ra);
                if (nprod == 3)
                    LDSM4(al[mi][0], al[mi][1], al[mi][2], al[mi][3], aLb + ra);
            }
#pragma unroll
            for (int pi = 0; pi < 2; pi++) {
                uint32_t rb = (uint32_t)(pi * 16 + bnsub + l7) * RSB + bkb2;
                LDSM4(bh[pi][0], bh[pi][1], bh[pi][2], bh[pi][3], bHb + rb);
                if (nprod == 3)
                    LDSM4(bl[pi][0], bl[pi][1], bl[pi][2], bl[pi][3], bLb + rb);
            }
#pragma unroll
            for (int mi = 0; mi < 4; mi++) {
#pragma unroll
                for (int ni = 0; ni < 4; ni++) {
                    const int pi = ni >> 1, j = (ni & 1) * 2;
                    float* a4 = acc[mi][ni];
                    MMA16816(a4[0], a4[1], a4[2], a4[3],
                             ah[mi][0], ah[mi][1], ah[mi][2], ah[mi][3],
                             bh[pi][j], bh[pi][j + 1]);
                    if (nprod == 3) {
                        MMA16816(a4[0], a4[1], a4[2], a4[3],
                                 ah[mi][0], ah[mi][1], ah[mi][2], ah[mi][3],
                                 bl[pi][j], bl[pi][j + 1]);
                        MMA16816(a4[0], a4[1], a4[2], a4[3],
                                 al[mi][0], al[mi][1], al[mi][2], al[mi][3],
                                 bh[pi][j], bh[pi][j + 1]);
                    }
                }
            }
        }
        __syncthreads();
    }

    // output pointer select
    float* of = Cf;
    h16 *oh = Ch, *ol = Cl;
    if (mode == 0) {
        if (p == 0)      { of = nullptr; oh = Ch;  ol = Cl;  }
        else if (p == 1) { of = nullptr; oh = Kh2; ol = Kl2; }
        // p == 2: of = Cf (Vf)
    }

    // epilogue: direct register -> global stores
    const int gr = lane >> 2;
    const int gc = (lane & 3) << 1;
#pragma unroll
    for (int mi = 0; mi < 4; mi++) {
#pragma unroll
        for (int ni = 0; ni < 4; ni++) {
            const int r  = m0 + wm * 64 + mi * 16 + gr;
            const int cc = n0 + wn * 32 + ni * 8 + gc;
            float v0 = acc[mi][ni][0] * scale;
            float v1 = acc[mi][ni][1] * scale;
            float v2 = acc[mi][ni][2] * scale;
            float v3 = acc[mi][ni][3] * scale;
            if (of) {
                *(float2*)&of[(size_t)r * ldc + cc]       = make_float2(v0, v1);
                *(float2*)&of[(size_t)(r + 8) * ldc + cc] = make_float2(v2, v3);
            } else {
                h16 h0 = __float2half_rn(v0);
                h16 h1 = __float2half_rn(v1);
                h16 h2 = __float2half_rn(v2);
                h16 h3 = __float2half_rn(v3);
                __half2 hi01 = __halves2half2(h0, h1);
                __half2 hi23 = __halves2half2(h2, h3);
                __half2 lo01 = __halves2half2(
                    __float2half_rn(v0 - __half2float(h0)),
                    __float2half_rn(v1 - __half2float(h1)));
                __half2 lo23 = __halves2half2(
                    __float2half_rn(v2 - __half2float(h2)),
                    __float2half_rn(v3 - __half2float(h3)));
                *(__half2*)&oh[(size_t)r * ldc + cc]       = hi01;
                *(__half2*)&ol[(size_t)r * ldc + cc]       = lo01;
                *(__half2*)&oh[(size_t)(r + 8) * ldc + cc] = hi23;
                *(__half2*)&ol[(size_t)(r + 8) * ldc + cc] = lo23;
            }
        }
    }
}

// ---------------- host launcher ---------------------------------------------
extern "C" void kernel_launch(void* const* d_in, const int* in_sizes, int n_in,
                              void* d_out, int out_size)
{
    const float* x  = (const float*)d_in[0];
    const float* Wq = (const float*)d_in[1];
    const float* Wk = (const float*)d_in[2];
    const float* Wv = (const float*)d_in[3];
    float* out = (float*)d_out;

    h16 *xh, *xl, *Wth, *Wtl, *Qh, *Ql, *Kh, *Kl, *Vth, *Ph;
    float *Vf, *Pf;
    cudaGetSymbolAddress((void**)&xh,  g_xh);
    cudaGetSymbolAddress((void**)&xl,  g_xl);
    cudaGetSymbolAddress((void**)&Wth, g_Wth);
    cudaGetSymbolAddress((void**)&Wtl, g_Wtl);
    cudaGetSymbolAddress((void**)&Qh,  g_Qh);
    cudaGetSymbolAddress((void**)&Ql,  g_Ql);
    cudaGetSymbolAddress((void**)&Kh,  g_Kh);
    cudaGetSymbolAddress((void**)&Kl,  g_Kl);
    cudaGetSymbolAddress((void**)&Vf,  g_Vf);
    cudaGetSymbolAddress((void**)&Vth, g_Vth);
    cudaGetSymbolAddress((void**)&Pf,  g_Pf);
    cudaGetSymbolAddress((void**)&Ph,  g_Ph);

    cudaFuncSetAttribute(mm_gemm, cudaFuncAttributeMaxDynamicSharedMemorySize, SMEM3);

    // 1) split x
    split_f32<<<2048, 256>>>(x, xh, xl, S_LEN * E_DIM);
    // 2) all weight transposes in one launch (Wv: hi only)
    transpose_split_w<<<dim3(32, 32, 3), 256>>>(Wq, Wk, Wv, Wth, Wtl);
    // 3) fused QKV projections: Q,K 3-product split out; V 1-product fp32 out
    mm_gemm<<<768, 256, SMEM3>>>(xh, xl, Wth, Wtl,
                                 Vf, Qh, Ql, Kh, Kl, E_DIM, D_DIM, 1.0f, 0, 3);
    // 4) transpose V: V[S,D] -> Vt[D,S], single fp16
    transpose_half<<<dim3(D_DIM / 32, S_LEN / 32), 256>>>(Vf, Vth, S_LEN, D_DIM);
    // 5) causal scores (lower-tri blocks), scale 1/32, fp32 out
    mm_gemm<<<528, 256, SMEM3>>>(Qh, Ql, Kh, Kl,
                                 Pf, nullptr, nullptr, nullptr, nullptr,
                                 D_DIM, S_LEN, 1.0f / 32.0f, 1, 3);
    // 6) softmax -> fp16 probs (zero-padded to 128 boundary)
    softmax_half<<<S_LEN, 256>>>(Pf, Ph);
    // 7) out = P @ V  (causal, single-product fp16, heavy-first zigzag)
    mm_gemm<<<256, 256, SMEM1>>>(Ph, nullptr, Vth, nullptr,
                                 out, nullptr, nullptr, nullptr, nullptr,
                                 S_LEN, D_DIM, 1.0f, 2, 1);
}

// round 7
// speedup vs baseline: 1.1946x; 1.1946x over previous
#include <cuda_runtime.h>
#include <cuda_fp16.h>
#include <cstdint>
#include <math.h>

#define S_LEN 4096
#define E_DIM 1024
#define D_DIM 1024

typedef __half h16;

// ---------------- scratch (device globals; no allocation allowed) ----------
__device__ h16   g_xh[(size_t)S_LEN * E_DIM];
__device__ h16   g_xl[(size_t)S_LEN * E_DIM];
__device__ h16   g_Wth[3][(size_t)D_DIM * E_DIM];   // W^T hi (stacked q,k,v)
__device__ h16   g_Wtl[3][(size_t)D_DIM * E_DIM];   // W^T lo (v slot unused)
__device__ h16   g_Qh[(size_t)S_LEN * D_DIM];
__device__ h16   g_Ql[(size_t)S_LEN * D_DIM];
__device__ h16   g_Kh[(size_t)S_LEN * D_DIM];
__device__ h16   g_Kl[(size_t)S_LEN * D_DIM];
__device__ float g_Vf[(size_t)S_LEN * D_DIM];
__device__ h16   g_Vth[(size_t)D_DIM * S_LEN];      // V^T fp16 (single)
__device__ float g_Pf[(size_t)S_LEN * S_LEN];       // raw scores (lower tri)
__device__ h16   g_Ph[(size_t)S_LEN * S_LEN];       // probs fp16 (single)

// ---------------- PTX helpers (sm_80-compatible only) -----------------------
__device__ __forceinline__ uint32_t smem_u32(const void* p) {
    uint32_t a;
    asm("{ .reg .u64 t; cvta.to.shared.u64 t, %1; cvt.u32.u64 %0, t; }" : "=r"(a) : "l"(p));
    return a;
}

#define CP_ASYNC16(saddr, gaddr) \
    asm volatile("cp.async.cg.shared.global [%0], [%1], 16;" \
                 :: "r"(saddr), "l"(gaddr) : "memory")
#define CP_COMMIT() asm volatile("cp.async.commit_group;" ::: "memory")
#define CP_WAIT(N)  asm volatile("cp.async.wait_group %0;" :: "n"(N) : "memory")

#define LDSM4(r0, r1, r2, r3, addr) \
    asm volatile("ldmatrix.sync.aligned.m8n8.x4.shared.b16 {%0,%1,%2,%3}, [%4];" \
                 : "=r"(r0), "=r"(r1), "=r"(r2), "=r"(r3) : "r"(addr))

#define MMA16816(c0, c1, c2, c3, a0, a1, a2, a3, b0, b1) \
    asm volatile("mma.sync.aligned.m16n8k16.row.col.f32.f16.f16.f32 " \
                 "{%0,%1,%2,%3}, {%4,%5,%6,%7}, {%8,%9}, {%0,%1,%2,%3};" \
                 : "+f"(c0), "+f"(c1), "+f"(c2), "+f"(c3) \
                 : "r"(a0), "r"(a1), "r"(a2), "r"(a3), "r"(b0), "r"(b1))

// ---------------- aux kernels -----------------------------------------------
__global__ __launch_bounds__(256)
void split_f32(const float* __restrict__ src, h16* __restrict__ h,
               h16* __restrict__ l, int n)
{
    for (int i = blockIdx.x * 256 + threadIdx.x; i < n; i += gridDim.x * 256) {
        float v = src[i];
        h16 a = __float2half_rn(v);
        h[i] = a;
        l[i] = __float2half_rn(v - __half2float(a));
    }
}

// All three weight transposes in one launch (z selects); z==2 (Wv) skips lo.
__global__ __launch_bounds__(256)
void transpose_split_w(const float* __restrict__ Wq, const float* __restrict__ Wk,
                       const float* __restrict__ Wv,
                       h16* __restrict__ dh, h16* __restrict__ dl)
{
    const int z = blockIdx.z;
    const float* src = (z == 0) ? Wq : (z == 1) ? Wk : Wv;
    const size_t WSZ = (size_t)D_DIM * E_DIM;
    h16* dhp = dh + (size_t)z * WSZ;
    h16* dlp = dl + (size_t)z * WSZ;

    __shared__ float t[32][33];
    const int bx = blockIdx.x * 32;  // col of src (D)
    const int by = blockIdx.y * 32;  // row of src (E)
    const int tx = threadIdx.x & 31, ty = threadIdx.x >> 5;
#pragma unroll
    for (int j = ty; j < 32; j += 8)
        t[j][tx] = src[(size_t)(by + j) * D_DIM + bx + tx];
    __syncthreads();
#pragma unroll
    for (int j = ty; j < 32; j += 8) {
        float v = t[tx][j];
        size_t o = (size_t)(bx + j) * E_DIM + by + tx;
        h16 a = __float2half_rn(v);
        dhp[o] = a;
        if (z < 2) dlp[o] = __float2half_rn(v - __half2float(a));
    }
}

// V transpose (fp16 single): dst[c][r] = h(src[r][c])
__global__ __launch_bounds__(256)
void transpose_half(const float* __restrict__ src, h16* __restrict__ dh,
                    int R, int C)
{
    __shared__ float t[32][33];
    const int bx = blockIdx.x * 32;
    const int by = blockIdx.y * 32;
    const int tx = threadIdx.x & 31, ty = threadIdx.x >> 5;
#pragma unroll
    for (int j = ty; j < 32; j += 8)
        t[j][tx] = src[(size_t)(by + j) * C + bx + tx];
    __syncthreads();
#pragma unroll
    for (int j = ty; j < 32; j += 8)
        dh[(size_t)(bx + j) * R + by + tx] = __float2half_rn(t[tx][j]);
}

// causal softmax over raw scores Pf; writes fp16 probs, zero-padded to the
// 128-aligned block boundary (= kEnd consumed by the PV GEMM).
__global__ __launch_bounds__(256)
void softmax_half(float* __restrict__ Pf, h16* __restrict__ Ph)
{
    const int row = blockIdx.x;
    float* p = Pf + (size_t)row * S_LEN;
    h16* ph = Ph + (size_t)row * S_LEN;
    const int len = row + 1;
    const int tid = threadIdx.x, lane = tid & 31, warp = tid >> 5;
    __shared__ float red[8];
    __shared__ float bcast;

    float m = -3.4e38f;
    for (int j = tid; j < len; j += 256) m = fmaxf(m, p[j]);
#pragma unroll
    for (int o = 16; o; o >>= 1) m = fmaxf(m, __shfl_xor_sync(0xffffffffu, m, o));
    if (lane == 0) red[warp] = m;
    __syncthreads();
    if (tid == 0) {
        float v = red[0];
#pragma unroll
        for (int i = 1; i < 8; i++) v = fmaxf(v, red[i]);
        bcast = v;
    }
    __syncthreads();
    m = bcast;
    __syncthreads();

    float s = 0.0f;
    for (int j = tid; j < len; j += 256) {
        float e = expf(p[j] - m);
        p[j] = e;
        s += e;
    }
#pragma unroll
    for (int o = 16; o; o >>= 1) s += __shfl_xor_sync(0xffffffffu, s, o);
    if (lane == 0) red[warp] = s;
    __syncthreads();
    if (tid == 0) {
        float v = 0.0f;
#pragma unroll
        for (int i = 0; i < 8; i++) v += red[i];
        bcast = 1.0f / v;
    }
    __syncthreads();
    const float inv = bcast;

    for (int j = tid; j < len; j += 256)
        ph[j] = __float2half_rn(p[j] * inv);
    const int kpad = ((row >> 7) + 1) << 7;
    const h16 z = __float2half_rn(0.0f);
    for (int j = len + tid; j < kpad; j += 256) ph[j] = z;
}

// ---------------- split-fp16 GEMM via mma.sync (compile-time NPROD) ----------
// NPROD=3: C = scale*(AhBh + AhBl + AlBh)   NPROD=1: C = scale*AhBh
// mode 0: fused QK projection, grid=512: p=t>>8 -> {Q split, K split} out.
// mode 1: triangular 1D grid (scores), fp32 out Cf.
// mode 2: causal PV, kEnd=(br+1)*128, heavy-first zigzag remap, fp32 out Cf.
// mode 3: plain full-K GEMM, grid 1D (br=t>>3, bc=t&7), fp32 out Cf.
#define RSB     80                   // smem row stride bytes (64B data + 16B pad)
#define TILE_B  (128 * RSB)          // 10240

template <int NPROD>
__global__ __launch_bounds__(256, 2)
void mm_gemm(const h16* __restrict__ Ah, const h16* __restrict__ Al,
             const h16* __restrict__ Bh, const h16* __restrict__ Bl,
             float* __restrict__ Cf, h16* __restrict__ Ch, h16* __restrict__ Cl,
             h16* __restrict__ Kh2, h16* __restrict__ Kl2,
             int Ktot, int ldc, float scale, int mode)
{
    constexpr int NTILES  = (NPROD == 3) ? 4 : 2;
    constexpr uint32_t STAGE_B = NTILES * TILE_B;

    extern __shared__ char smem[];
    const int tid = threadIdx.x;
    const int wid = tid >> 5;
    const int lane = tid & 31;
    const int wm = wid >> 2;          // 0..1  (64-row slabs)
    const int wn = wid & 3;           // 0..3  (32-col slabs)

    int br, bc, p = 0;
    if (mode == 1) {
        int t = blockIdx.x;
        br = (int)((sqrtf(8.0f * (float)t + 1.0f) - 1.0f) * 0.5f);
        while ((br + 1) * (br + 2) / 2 <= t) br++;
        while (br * (br + 1) / 2 > t) br--;
        bc = t - br * (br + 1) / 2;
    } else if (mode == 2) {
        int t = blockIdx.x;
        int r = (t < 148) ? t : (403 - t);
        br = 31 - (r >> 3);
        bc = r & 7;
    } else if (mode == 3) {
        int t = blockIdx.x;
        br = t >> 3;
        bc = t & 7;
    } else {
        int t = blockIdx.x;
        p = t >> 8;
        int r = t & 255;
        br = r >> 3;
        bc = r & 7;
    }
    const int m0 = br * 128, n0 = bc * 128;
    const int kEnd = (mode == 2) ? (br + 1) * 128 : Ktot;
    const int NC = kEnd / 32;

    const h16* Bhp = Bh + (size_t)p * ((size_t)D_DIM * E_DIM);
    const h16* Blp = (NPROD == 3) ? (Bl + (size_t)p * ((size_t)D_DIM * E_DIM)) : nullptr;

    const uint32_t tiles = (smem_u32(smem) + 127u) & ~127u;

    float acc[4][4][4];
#pragma unroll
    for (int i = 0; i < 4; i++)
#pragma unroll
        for (int j = 0; j < 4; j++)
#pragma unroll
            for (int k = 0; k < 4; k++) acc[i][j][k] = 0.0f;

    auto load_stage = [&](int c) {
        const uint32_t st = tiles + (uint32_t)(c & 1) * STAGE_B;
        const int k0 = c * 32;
        const h16* srcs[NTILES];
        if (NPROD == 3) {
            srcs[0] = Ah  + (size_t)m0 * Ktot + k0;
            srcs[1] = Al  + (size_t)m0 * Ktot + k0;
            srcs[2] = Bhp + (size_t)n0 * Ktot + k0;
            srcs[3] = Blp + (size_t)n0 * Ktot + k0;
        } else {
            srcs[0] = Ah  + (size_t)m0 * Ktot + k0;
            srcs[1] = Bhp + (size_t)n0 * Ktot + k0;
        }
#pragma unroll
        for (int t = 0; t < NTILES; t++) {
#pragma unroll
            for (int j2 = 0; j2 < 2; j2++) {
                int j = tid + j2 * 256;          // 0..511
                int row = j >> 2, ck = j & 3;
                const void* g = srcs[t] + (size_t)row * Ktot + ck * 8;
                uint32_t s = st + (uint32_t)t * TILE_B + row * RSB + ck * 16;
                CP_ASYNC16(s, g);
            }
        }
        CP_COMMIT();
    };

    load_stage(0);

    const int lr15 = lane & 15;
    const int lhi16 = (lane >> 4) * 16;          // A chunk-half byte offset
    const int l7 = lane & 7;
    const int bmat = lane >> 3;                  // 0..3
    const int bnsub = (bmat >> 1) * 8;
    const int bkb = (bmat & 1) * 16;

    for (int c = 0; c < NC; c++) {
        if (c + 1 < NC) { load_stage(c + 1); CP_WAIT(1); }
        else            { CP_WAIT(0); }
        __syncthreads();

        const uint32_t st = tiles + (uint32_t)(c & 1) * STAGE_B;
        const uint32_t aHb = st + (uint32_t)(wm * 64) * RSB;
        const uint32_t aLb = aHb + TILE_B;                       // NPROD==3 only
        const uint32_t bHb = st + (uint32_t)(NTILES / 2) * TILE_B
                                + (uint32_t)(wn * 32) * RSB;
        const uint32_t bLb = bHb + TILE_B;                       // NPROD==3 only

#pragma unroll
        for (int ks = 0; ks < 2; ks++) {
            const uint32_t akb  = (uint32_t)(ks * 32 + lhi16);
            const uint32_t bkb2 = (uint32_t)(ks * 32) + bkb;

            uint32_t ah[4][4], al[4][4], bh[2][4], bl[2][4];
#pragma unroll
            for (int mi = 0; mi < 4; mi++) {
                uint32_t ra = (uint32_t)(mi * 16 + lr15) * RSB + akb;
                LDSM4(ah[mi][0], ah[mi][1], ah[mi][2], ah[mi][3], aHb + ra);
                if (NPROD == 3)
                    LDSM4(al[mi][0], al[mi][1], al[mi][2], al[mi][3], aLb + ra);
            }
#pragma unroll
            for (int pi = 0; pi < 2; pi++) {
                uint32_t rb = (uint32_t)(pi * 16 + bnsub + l7) * RSB + bkb2;
                LDSM4(bh[pi][0], bh[pi][1], bh[pi][2], bh[pi][3], bHb + rb);
                if (NPROD == 3)
                    LDSM4(bl[pi][0], bl[pi][1], bl[pi][2], bl[pi][3], bLb + rb);
            }
#pragma unroll
            for (int mi = 0; mi < 4; mi++) {
#pragma unroll
                for (int ni = 0; ni < 4; ni++) {
                    const int pi = ni >> 1, j = (ni & 1) * 2;
                    float* a4 = acc[mi][ni];
                    MMA16816(a4[0], a4[1], a4[2], a4[3],
                             ah[mi][0], ah[mi][1], ah[mi][2], ah[mi][3],
                             bh[pi][j], bh[pi][j + 1]);
                    if (NPROD == 3) {
                        MMA16816(a4[0], a4[1], a4[2], a4[3],
                                 ah[mi][0], ah[mi][1], ah[mi][2], ah[mi][3],
                                 bl[pi][j], bl[pi][j + 1]);
                        MMA16816(a4[0], a4[1], a4[2], a4[3],
                                 al[mi][0], al[mi][1], al[mi][2], al[mi][3],
                                 bh[pi][j], bh[pi][j + 1]);
                    }
                }
            }
        }
        __syncthreads();
    }

    // output pointer select
    float* of = Cf;
    h16 *oh = Ch, *ol = Cl;
    if (mode == 0) {
        if (p == 0)      { of = nullptr; oh = Ch;  ol = Cl;  }
        else             { of = nullptr; oh = Kh2; ol = Kl2; }
    }

    // epilogue: direct register -> global stores
    const int gr = lane >> 2;
    const int gc = (lane & 3) << 1;
#pragma unroll
    for (int mi = 0; mi < 4; mi++) {
#pragma unroll
        for (int ni = 0; ni < 4; ni++) {
            const int r  = m0 + wm * 64 + mi * 16 + gr;
            const int cc = n0 + wn * 32 + ni * 8 + gc;
            float v0 = acc[mi][ni][0] * scale;
            float v1 = acc[mi][ni][1] * scale;
            float v2 = acc[mi][ni][2] * scale;
            float v3 = acc[mi][ni][3] * scale;
            if (of) {
                *(float2*)&of[(size_t)r * ldc + cc]       = make_float2(v0, v1);
                *(float2*)&of[(size_t)(r + 8) * ldc + cc] = make_float2(v2, v3);
            } else {
                h16 h0 = __float2half_rn(v0);
                h16 h1 = __float2half_rn(v1);
                h16 h2 = __float2half_rn(v2);
                h16 h3 = __float2half_rn(v3);
                __half2 hi01 = __halves2half2(h0, h1);
                __half2 hi23 = __halves2half2(h2, h3);
                __half2 lo01 = __halves2half2(
                    __float2half_rn(v0 - __half2float(h0)),
                    __float2half_rn(v1 - __half2float(h1)));
                __half2 lo23 = __halves2half2(
                    __float2half_rn(v2 - __half2float(h2)),
                    __float2half_rn(v3 - __half2float(h3)));
                *(__half2*)&oh[(size_t)r * ldc + cc]       = hi01;
                *(__half2*)&ol[(size_t)r * ldc + cc]       = lo01;
                *(__half2*)&oh[(size_t)(r + 8) * ldc + cc] = hi23;
                *(__half2*)&ol[(size_t)(r + 8) * ldc + cc] = lo23;
            }
        }
    }
}

#define SMEM3 (2 * 4 * TILE_B + 128)   // 82048
#define SMEM1 (2 * 2 * TILE_B + 128)   // 41088

// ---------------- host launcher ---------------------------------------------
extern "C" void kernel_launch(void* const* d_in, const int* in_sizes, int n_in,
                              void* d_out, int out_size)
{
    const float* x  = (const float*)d_in[0];
    const float* Wq = (const float*)d_in[1];
    const float* Wk = (const float*)d_in[2];
    const float* Wv = (const float*)d_in[3];
    float* out = (float*)d_out;

    h16 *xh, *xl, *Wth, *Wtl, *Qh, *Ql, *Kh, *Kl, *Vth, *Ph;
    float *Vf, *Pf;
    cudaGetSymbolAddress((void**)&xh,  g_xh);
    cudaGetSymbolAddress((void**)&xl,  g_xl);
    cudaGetSymbolAddress((void**)&Wth, g_Wth);
    cudaGetSymbolAddress((void**)&Wtl, g_Wtl);
    cudaGetSymbolAddress((void**)&Qh,  g_Qh);
    cudaGetSymbolAddress((void**)&Ql,  g_Ql);
    cudaGetSymbolAddress((void**)&Kh,  g_Kh);
    cudaGetSymbolAddress((void**)&Kl,  g_Kl);
    cudaGetSymbolAddress((void**)&Vf,  g_Vf);
    cudaGetSymbolAddress((void**)&Vth, g_Vth);
    cudaGetSymbolAddress((void**)&Pf,  g_Pf);
    cudaGetSymbolAddress((void**)&Ph,  g_Ph);

    cudaFuncSetAttribute(mm_gemm<3>, cudaFuncAttributeMaxDynamicSharedMemorySize, SMEM3);
    cudaFuncSetAttribute(mm_gemm<1>, cudaFuncAttributeMaxDynamicSharedMemorySize, SMEM1);

    const size_t WSZ = (size_t)D_DIM * E_DIM;

    // 1) split x
    split_f32<<<2048, 256>>>(x, xh, xl, S_LEN * E_DIM);
    // 2) all weight transposes in one launch (Wv: hi only)
    transpose_split_w<<<dim3(32, 32, 3), 256>>>(Wq, Wk, Wv, Wth, Wtl);
    // 3a) fused QK projections (3-product, split outputs)
    mm_gemm<3><<<512, 256, SMEM3>>>(xh, xl, Wth, Wtl,
                                    nullptr, Qh, Ql, Kh, Kl, E_DIM, D_DIM, 1.0f, 0);
    // 3b) V projection (1-product, fp32 out)
    mm_gemm<1><<<256, 256, SMEM1>>>(xh, nullptr, Wth + 2 * WSZ, nullptr,
                                    Vf, nullptr, nullptr, nullptr, nullptr,
                                    E_DIM, D_DIM, 1.0f, 3);
    // 4) transpose V: V[S,D] -> Vt[D,S], single fp16
    transpose_half<<<dim3(D_DIM / 32, S_LEN / 32), 256>>>(Vf, Vth, S_LEN, D_DIM);
    // 5) causal scores (lower-tri blocks), scale 1/32, fp32 out
    mm_gemm<3><<<528, 256, SMEM3>>>(Qh, Ql, Kh, Kl,
                                    Pf, nullptr, nullptr, nullptr, nullptr,
                                    D_DIM, S_LEN, 1.0f / 32.0f, 1);
    // 6) softmax -> fp16 probs (zero-padded to 128 boundary)
    softmax_half<<<S_LEN, 256>>>(Pf, Ph);
    // 7) out = P @ V  (causal, single-product fp16, heavy-first zigzag)
    mm_gemm<1><<<256, 256, SMEM1>>>(Ph, nullptr, Vth, nullptr,
                                    out, nullptr, nullptr, nullptr, nullptr,
                                    S_LEN, D_DIM, 1.0f, 2);
}

// round 8
// speedup vs baseline: 1.2553x; 1.0508x over previous
#include <cuda_runtime.h>
#include <cuda_fp16.h>
#include <cstdint>
#include <math.h>

#define S_LEN 4096
#define E_DIM 1024
#define D_DIM 1024

typedef __half h16;

// ---------------- scratch (device globals; no allocation allowed) ----------
__device__ h16   g_xh[(size_t)S_LEN * E_DIM];
__device__ h16   g_xl[(size_t)S_LEN * E_DIM];
__device__ h16   g_Wth[3][(size_t)D_DIM * E_DIM];   // W^T hi (stacked q,k,v)
__device__ h16   g_Wtl[3][(size_t)D_DIM * E_DIM];   // W^T lo (v slot unused)
__device__ h16   g_Qh[(size_t)S_LEN * D_DIM];
__device__ h16   g_Ql[(size_t)S_LEN * D_DIM];
__device__ h16   g_Kh[(size_t)S_LEN * D_DIM];
__device__ h16   g_Kl[(size_t)S_LEN * D_DIM];
__device__ h16   g_Vth[(size_t)D_DIM * S_LEN];      // V^T fp16 (written directly)
__device__ float g_Pf[(size_t)S_LEN * S_LEN];       // raw scores (lower tri)
__device__ h16   g_Ph[(size_t)S_LEN * S_LEN];       // unnormalized exp fp16
__device__ int   g_rowmax[S_LEN];                   // encoded fp32 row max
__device__ float g_rowsum[S_LEN];                   // softmax denominator

// ---------------- PTX helpers (sm_80-compatible only) -----------------------
__device__ __forceinline__ uint32_t smem_u32(const void* p) {
    uint32_t a;
    asm("{ .reg .u64 t; cvta.to.shared.u64 t, %1; cvt.u32.u64 %0, t; }" : "=r"(a) : "l"(p));
    return a;
}

#define CP_ASYNC16(saddr, gaddr) \
    asm volatile("cp.async.cg.shared.global [%0], [%1], 16;" \
                 :: "r"(saddr), "l"(gaddr) : "memory")
#define CP_COMMIT() asm volatile("cp.async.commit_group;" ::: "memory")
#define CP_WAIT(N)  asm volatile("cp.async.wait_group %0;" :: "n"(N) : "memory")

#define LDSM4(r0, r1, r2, r3, addr) \
    asm volatile("ldmatrix.sync.aligned.m8n8.x4.shared.b16 {%0,%1,%2,%3}, [%4];" \
                 : "=r"(r0), "=r"(r1), "=r"(r2), "=r"(r3) : "r"(addr))

#define MMA16816(c0, c1, c2, c3, a0, a1, a2, a3, b0, b1) \
    asm volatile("mma.sync.aligned.m16n8k16.row.col.f32.f16.f16.f32 " \
                 "{%0,%1,%2,%3}, {%4,%5,%6,%7}, {%8,%9}, {%0,%1,%2,%3};" \
                 : "+f"(c0), "+f"(c1), "+f"(c2), "+f"(c3) \
                 : "r"(a0), "r"(a1), "r"(a2), "r"(a3), "r"(b0), "r"(b1))

// monotone int encoding of fp32 for atomicMax
__device__ __forceinline__ int encf(float x) {
    int i = __float_as_int(x);
    return (i >= 0) ? i : (i ^ 0x7FFFFFFF);
}
__device__ __forceinline__ float decf(int i) {
    return __int_as_float((i >= 0) ? i : (i ^ 0x7FFFFFFF));
}

// ---------------- aux kernels -----------------------------------------------
__global__ __launch_bounds__(256)
void split_f32(const float* __restrict__ src, h16* __restrict__ h,
               h16* __restrict__ l, int n)
{
    int g = blockIdx.x * 256 + threadIdx.x;
    if (g < S_LEN) g_rowmax[g] = 0x80000000;   // INT_MIN, re-init every call
    for (int i = g; i < n; i += gridDim.x * 256) {
        float v = src[i];
        h16 a = __float2half_rn(v);
        h[i] = a;
        l[i] = __float2half_rn(v - __half2float(a));
    }
}

// All three weight transposes in one launch (z selects); z==2 (Wv) skips lo.
__global__ __launch_bounds__(256)
void transpose_split_w(const float* __restrict__ Wq, const float* __restrict__ Wk,
                       const float* __restrict__ Wv,
                       h16* __restrict__ dh, h16* __restrict__ dl)
{
    const int z = blockIdx.z;
    const float* src = (z == 0) ? Wq : (z == 1) ? Wk : Wv;
    const size_t WSZ = (size_t)D_DIM * E_DIM;
    h16* dhp = dh + (size_t)z * WSZ;
    h16* dlp = dl + (size_t)z * WSZ;

    __shared__ float t[32][33];
    const int bx = blockIdx.x * 32;
    const int by = blockIdx.y * 32;
    const int tx = threadIdx.x & 31, ty = threadIdx.x >> 5;
#pragma unroll
    for (int j = ty; j < 32; j += 8)
        t[j][tx] = src[(size_t)(by + j) * D_DIM + bx + tx];
    __syncthreads();
#pragma unroll
    for (int j = ty; j < 32; j += 8) {
        float v = t[tx][j];
        size_t o = (size_t)(bx + j) * E_DIM + by + tx;
        h16 a = __float2half_rn(v);
        dhp[o] = a;
        if (z < 2) dlp[o] = __float2half_rn(v - __half2float(a));
    }
}

// single-pass softmax: Ph = exp(Pf - rowmax) (unnormalized), rowsum out.
__global__ __launch_bounds__(256)
void softmax_onepass(const float* __restrict__ Pf, h16* __restrict__ Ph)
{
    const int row = blockIdx.x;
    const float* p = Pf + (size_t)row * S_LEN;
    h16* ph = Ph + (size_t)row * S_LEN;
    const int len = row + 1;
    const int tid = threadIdx.x, lane = tid & 31, warp = tid >> 5;
    __shared__ float red[8];

    const float m = decf(g_rowmax[row]);

    float s = 0.0f;
    for (int j = tid; j < len; j += 256) {
        float e = expf(p[j] - m);
        ph[j] = __float2half_rn(e);
        s += e;
    }
#pragma unroll
    for (int o = 16; o; o >>= 1) s += __shfl_xor_sync(0xffffffffu, s, o);
    if (lane == 0) red[warp] = s;
    __syncthreads();
    if (tid == 0) {
        float v = 0.0f;
#pragma unroll
        for (int i = 0; i < 8; i++) v += red[i];
        g_rowsum[row] = v;
    }
    const int kpad = ((row >> 7) + 1) << 7;
    const h16 z = __float2half_rn(0.0f);
    for (int j = len + tid; j < kpad; j += 256) ph[j] = z;
}

// ---------------- GEMM core (compile-time NPROD) -----------------------------
// acc += (A0 B0^T) [+ A0 B1^T + A1 B0^T if NPROD==3]; A/B rows K-major,
// pre-offset to the tile origin; row length Ktot; NC chunks of K=32.
#define RSB     80                   // smem row stride bytes (64B data + 16B pad)
#define TILE_B  (128 * RSB)          // 10240
#define SMEM3   (2 * 4 * TILE_B + 128)   // 82048
#define SMEM1   (2 * 2 * TILE_B + 128)   // 41088

template <int NPROD>
__device__ __forceinline__ void gemm_core(
    uint32_t tiles, const h16* __restrict__ A0, const h16* __restrict__ A1,
    const h16* __restrict__ B0, const h16* __restrict__ B1,
    int Ktot, int NC, float (&acc)[4][4][4])
{
    constexpr int NTILES = (NPROD == 3) ? 4 : 2;
    constexpr uint32_t STAGE_B = NTILES * TILE_B;

    const int tid = threadIdx.x;
    const int wid = tid >> 5;
    const int lane = tid & 31;
    const int wm = wid >> 2;
    const int wn = wid & 3;

#pragma unroll
    for (int i = 0; i < 4; i++)
#pragma unroll
        for (int j = 0; j < 4; j++)
#pragma unroll
            for (int k = 0; k < 4; k++) acc[i][j][k] = 0.0f;

    auto load_stage = [&](int c) {
        const uint32_t st = tiles + (uint32_t)(c & 1) * STAGE_B;
        const int k0 = c * 32;
        const h16* srcs[NTILES];
        if (NPROD == 3) {
            srcs[0] = A0 + k0; srcs[1] = A1 + k0;
            srcs[2] = B0 + k0; srcs[3] = B1 + k0;
        } else {
            srcs[0] = A0 + k0; srcs[1] = B0 + k0;
        }
#pragma unroll
        for (int t = 0; t < NTILES; t++) {
#pragma unroll
            for (int j2 = 0; j2 < 2; j2++) {
                int j = tid + j2 * 256;
                int row = j >> 2, ck = j & 3;
                const void* g = srcs[t] + (size_t)row * Ktot + ck * 8;
                uint32_t s = st + (uint32_t)t * TILE_B + row * RSB + ck * 16;
                CP_ASYNC16(s, g);
            }
        }
        CP_COMMIT();
    };

    load_stage(0);

    const int lr15 = lane & 15;
    const int lhi16 = (lane >> 4) * 16;
    const int l7 = lane & 7;
    const int bmat = lane >> 3;
    const int bnsub = (bmat >> 1) * 8;
    const int bkb = (bmat & 1) * 16;

    for (int c = 0; c < NC; c++) {
        if (c + 1 < NC) { load_stage(c + 1); CP_WAIT(1); }
        else            { CP_WAIT(0); }
        __syncthreads();

        const uint32_t st = tiles + (uint32_t)(c & 1) * STAGE_B;
        const uint32_t aHb = st + (uint32_t)(wm * 64) * RSB;
        const uint32_t aLb = aHb + TILE_B;
        const uint32_t bHb = st + (uint32_t)(NTILES / 2) * TILE_B
                                + (uint32_t)(wn * 32) * RSB;
        const uint32_t bLb = bHb + TILE_B;

#pragma unroll
        for (int ks = 0; ks < 2; ks++) {
            const uint32_t akb  = (uint32_t)(ks * 32 + lhi16);
            const uint32_t bkb2 = (uint32_t)(ks * 32) + bkb;

            uint32_t ah[4][4], al[4][4], bh[2][4], bl[2][4];
#pragma unroll
            for (int mi = 0; mi < 4; mi++) {
                uint32_t ra = (uint32_t)(mi * 16 + lr15) * RSB + akb;
                LDSM4(ah[mi][0], ah[mi][1], ah[mi][2], ah[mi][3], aHb + ra);
                if (NPROD == 3)
                    LDSM4(al[mi][0], al[mi][1], al[mi][2], al[mi][3], aLb + ra);
            }
#pragma unroll
            for (int pi = 0; pi < 2; pi++) {
                uint32_t rb = (uint32_t)(pi * 16 + bnsub + l7) * RSB + bkb2;
                LDSM4(bh[pi][0], bh[pi][1], bh[pi][2], bh[pi][3], bHb + rb);
                if (NPROD == 3)
                    LDSM4(bl[pi][0], bl[pi][1], bl[pi][2], bl[pi][3], bLb + rb);
            }
#pragma unroll
            for (int mi = 0; mi < 4; mi++) {
#pragma unroll
                for (int ni = 0; ni < 4; ni++) {
                    const int pi = ni >> 1, j = (ni & 1) * 2;
                    float* a4 = acc[mi][ni];
                    MMA16816(a4[0], a4[1], a4[2], a4[3],
                             ah[mi][0], ah[mi][1], ah[mi][2], ah[mi][3],
                             bh[pi][j], bh[pi][j + 1]);
                    if (NPROD == 3) {
                        MMA16816(a4[0], a4[1], a4[2], a4[3],
                                 ah[mi][0], ah[mi][1], ah[mi][2], ah[mi][3],
                                 bl[pi][j], bl[pi][j + 1]);
                        MMA16816(a4[0], a4[1], a4[2], a4[3],
                                 al[mi][0], al[mi][1], al[mi][2], al[mi][3],
                                 bh[pi][j], bh[pi][j + 1]);
                    }
                }
            }
        }
        __syncthreads();
    }
}

// ---------------- kernels ----------------------------------------------------
// QK projection: grid 512, p=t>>8 -> Q or K, split-fp16 outputs.
__global__ __launch_bounds__(256, 2)
void mm_qk(const h16* __restrict__ xh, const h16* __restrict__ xl,
           const h16* __restrict__ Wth, const h16* __restrict__ Wtl)
{
    extern __shared__ char smem[];
    const uint32_t tiles = (smem_u32(smem) + 127u) & ~127u;
    const int t = blockIdx.x;
    const int p = t >> 8;
    const int r = t & 255;
    const int m0 = (r >> 3) * 128, n0 = (r & 7) * 128;
    const size_t WSZ = (size_t)D_DIM * E_DIM;

    float acc[4][4][4];
    gemm_core<3>(tiles,
                 xh + (size_t)m0 * E_DIM, xl + (size_t)m0 * E_DIM,
                 Wth + (size_t)p * WSZ + (size_t)n0 * E_DIM,
                 Wtl + (size_t)p * WSZ + (size_t)n0 * E_DIM,
                 E_DIM, E_DIM / 32, acc);

    h16* oh = p ? g_Kh : g_Qh;
    h16* ol = p ? g_Kl : g_Ql;
    const int lane = threadIdx.x & 31;
    const int wm = (threadIdx.x >> 5) >> 2, wn = (threadIdx.x >> 5) & 3;
    const int gr = lane >> 2, gc = (lane & 3) << 1;
#pragma unroll
    for (int mi = 0; mi < 4; mi++) {
#pragma unroll
        for (int ni = 0; ni < 4; ni++) {
            const int rr = m0 + wm * 64 + mi * 16 + gr;
            const int cc = n0 + wn * 32 + ni * 8 + gc;
            float v0 = acc[mi][ni][0], v1 = acc[mi][ni][1];
            float v2 = acc[mi][ni][2], v3 = acc[mi][ni][3];
            h16 h0 = __float2half_rn(v0), h1 = __float2half_rn(v1);
            h16 h2 = __float2half_rn(v2), h3 = __float2half_rn(v3);
            __half2 hi01 = __halves2half2(h0, h1);
            __half2 hi23 = __halves2half2(h2, h3);
            __half2 lo01 = __halves2half2(__float2half_rn(v0 - __half2float(h0)),
                                          __float2half_rn(v1 - __half2float(h1)));
            __half2 lo23 = __halves2half2(__float2half_rn(v2 - __half2float(h2)),
                                          __float2half_rn(v3 - __half2float(h3)));
            *(__half2*)&oh[(size_t)rr * D_DIM + cc]       = hi01;
            *(__half2*)&ol[(size_t)rr * D_DIM + cc]       = lo01;
            *(__half2*)&oh[(size_t)(rr + 8) * D_DIM + cc] = hi23;
            *(__half2*)&ol[(size_t)(rr + 8) * D_DIM + cc] = lo23;
        }
    }
}

// merged: t<528 -> causal scores (3-product, Pf + rowmax atomics)
//         t>=528 -> V^T projection (1-product, fp16 out to Vth)
__global__ __launch_bounds__(256, 2)
void mm_scores_v(const h16* __restrict__ xh,
                 const h16* __restrict__ Wvth)
{
    extern __shared__ char smem[];
    const uint32_t tiles = (smem_u32(smem) + 127u) & ~127u;
    const int lane = threadIdx.x & 31;
    const int wm = (threadIdx.x >> 5) >> 2, wn = (threadIdx.x >> 5) & 3;
    const int gr = lane >> 2, gc = (lane & 3) << 1;

    if (blockIdx.x < 528) {
        // ---- causal scores tile ----
        int t = blockIdx.x;
        int br = (int)((sqrtf(8.0f * (float)t + 1.0f) - 1.0f) * 0.5f);
        while ((br + 1) * (br + 2) / 2 <= t) br++;
        while (br * (br + 1) / 2 > t) br--;
        const int bc = t - br * (br + 1) / 2;
        const int m0 = br * 128, n0 = bc * 128;

        float acc[4][4][4];
        gemm_core<3>(tiles,
                     g_Qh + (size_t)m0 * D_DIM, g_Ql + (size_t)m0 * D_DIM,
                     g_Kh + (size_t)n0 * D_DIM, g_Kl + (size_t)n0 * D_DIM,
                     D_DIM, D_DIM / 32, acc);

        const bool diag = (bc == br);
        const float scale = 1.0f / 32.0f;
#pragma unroll
        for (int mi = 0; mi < 4; mi++) {
            const int r0 = m0 + wm * 64 + mi * 16 + gr;
            const int r1 = r0 + 8;
            float mx0 = -3.4e38f, mx1 = -3.4e38f;
#pragma unroll
            for (int ni = 0; ni < 4; ni++) {
                const int cc = n0 + wn * 32 + ni * 8 + gc;
                float v0 = acc[mi][ni][0] * scale;
                float v1 = acc[mi][ni][1] * scale;
                float v2 = acc[mi][ni][2] * scale;
                float v3 = acc[mi][ni][3] * scale;
                *(float2*)&g_Pf[(size_t)r0 * S_LEN + cc] = make_float2(v0, v1);
                *(float2*)&g_Pf[(size_t)r1 * S_LEN + cc] = make_float2(v2, v3);
                if (!diag || cc     <= r0) mx0 = fmaxf(mx0, v0);
                if (!diag || cc + 1 <= r0) mx0 = fmaxf(mx0, v1);
                if (!diag || cc     <= r1) mx1 = fmaxf(mx1, v2);
                if (!diag || cc + 1 <= r1) mx1 = fmaxf(mx1, v3);
            }
            mx0 = fmaxf(mx0, __shfl_xor_sync(0xffffffffu, mx0, 1));
            mx0 = fmaxf(mx0, __shfl_xor_sync(0xffffffffu, mx0, 2));
            mx1 = fmaxf(mx1, __shfl_xor_sync(0xffffffffu, mx1, 1));
            mx1 = fmaxf(mx1, __shfl_xor_sync(0xffffffffu, mx1, 2));
            if ((lane & 3) == 0) {
                atomicMax(&g_rowmax[r0], encf(mx0));
                atomicMax(&g_rowmax[r1], encf(mx1));
            }
        }
    } else {
        // ---- V^T projection tile: Vt[d][s] = sum_e Wv^T[d][e] x[s][e] ----
        const int u = blockIdx.x - 528;
        const int m0 = (u >> 5) * 128;   // d block (D_DIM/128 = 8)
        const int n0 = (u & 31) * 128;   // s block (S_LEN/128 = 32)

        float acc[4][4][4];
        gemm_core<1>(tiles,
                     Wvth + (size_t)m0 * E_DIM, nullptr,
                     xh + (size_t)n0 * E_DIM, nullptr,
                     E_DIM, E_DIM / 32, acc);

#pragma unroll
        for (int mi = 0; mi < 4; mi++) {
#pragma unroll
            for (int ni = 0; ni < 4; ni++) {
                const int rr = m0 + wm * 64 + mi * 16 + gr;
                const int cc = n0 + wn * 32 + ni * 8 + gc;
                __half2 a = __halves2half2(__float2half_rn(acc[mi][ni][0]),
                                           __float2half_rn(acc[mi][ni][1]));
                __half2 b = __halves2half2(__float2half_rn(acc[mi][ni][2]),
                                           __float2half_rn(acc[mi][ni][3]));
                *(__half2*)&g_Vth[(size_t)rr * S_LEN + cc]       = a;
                *(__half2*)&g_Vth[(size_t)(rr + 8) * S_LEN + cc] = b;
            }
        }
    }
}

// PV: causal, heavy-first zigzag; epilogue scales by 1/rowsum (softmax norm).
__global__ __launch_bounds__(256, 2)
void mm_pv(float* __restrict__ out)
{
    extern __shared__ char smem[];
    const uint32_t tiles = (smem_u32(smem) + 127u) & ~127u;
    const int t = blockIdx.x;
    const int r = (t < 148) ? t : (403 - t);
    const int br = 31 - (r >> 3);
    const int bc = r & 7;
    const int m0 = br * 128, n0 = bc * 128;
    const int NC = (br + 1) * 4;

    float acc[4][4][4];
    gemm_core<1>(tiles,
                 g_Ph + (size_t)m0 * S_LEN, nullptr,
                 g_Vth + (size_t)n0 * S_LEN, nullptr,
                 S_LEN, NC, acc);

    const int lane = threadIdx.x & 31;
    const int wm = (threadIdx.x >> 5) >> 2, wn = (threadIdx.x >> 5) & 3;
    const int gr = lane >> 2, gc = (lane & 3) << 1;
#pragma unroll
    for (int mi = 0; mi < 4; mi++) {
        const int r0 = m0 + wm * 64 + mi * 16 + gr;
        const float inv0 = 1.0f / g_rowsum[r0];
        const float inv1 = 1.0f / g_rowsum[r0 + 8];
#pragma unroll
        for (int ni = 0; ni < 4; ni++) {
            const int cc = n0 + wn * 32 + ni * 8 + gc;
            *(float2*)&out[(size_t)r0 * D_DIM + cc] =
                make_float2(acc[mi][ni][0] * inv0, acc[mi][ni][1] * inv0);
            *(float2*)&out[(size_t)(r0 + 8) * D_DIM + cc] =
                make_float2(acc[mi][ni][2] * inv1, acc[mi][ni][3] * inv1);
        }
    }
}

// ---------------- host launcher ---------------------------------------------
extern "C" void kernel_launch(void* const* d_in, const int* in_sizes, int n_in,
                              void* d_out, int out_size)
{
    const float* x  = (const float*)d_in[0];
    const float* Wq = (const float*)d_in[1];
    const float* Wk = (const float*)d_in[2];
    const float* Wv = (const float*)d_in[3];
    float* out = (float*)d_out;

    h16 *xh, *xl, *Wth, *Wtl, *Pf_h, *Ph;
    float *Pf;
    cudaGetSymbolAddress((void**)&xh,  g_xh);
    cudaGetSymbolAddress((void**)&xl,  g_xl);
    cudaGetSymbolAddress((void**)&Wth, g_Wth);
    cudaGetSymbolAddress((void**)&Wtl, g_Wtl);
    cudaGetSymbolAddress((void**)&Pf,  g_Pf);
    cudaGetSymbolAddress((void**)&Ph,  g_Ph);
    (void)Pf_h;

    cudaFuncSetAttribute(mm_qk,       cudaFuncAttributeMaxDynamicSharedMemorySize, SMEM3);
    cudaFuncSetAttribute(mm_scores_v, cudaFuncAttributeMaxDynamicSharedMemorySize, SMEM3);
    cudaFuncSetAttribute(mm_pv,       cudaFuncAttributeMaxDynamicSharedMemorySize, SMEM1);

    const size_t WSZ = (size_t)D_DIM * E_DIM;

    // 1) split x + re-init rowmax
    split_f32<<<2048, 256>>>(x, xh, xl, S_LEN * E_DIM);
    // 2) weight transposes (Wv: hi only)
    transpose_split_w<<<dim3(32, 32, 3), 256>>>(Wq, Wk, Wv, Wth, Wtl);
    // 3) fused QK projections (3-product, split outputs)
    mm_qk<<<512, 256, SMEM3>>>(xh, xl, Wth, Wtl);
    // 4) merged: causal scores (+ rowmax) then V^T projection in tail wave
    mm_scores_v<<<784, 256, SMEM3>>>(xh, Wth + 2 * WSZ);
    // 5) single-pass softmax: unnormalized exp fp16 + rowsum
    softmax_onepass<<<S_LEN, 256>>>(Pf, Ph);
    // 6) out = (P @ V) / rowsum  (causal, zigzag)
    mm_pv<<<256, 256, SMEM1>>>(out);
}

// round 9
// speedup vs baseline: 1.3648x; 1.0873x over previous
#include <cuda_runtime.h>
#include <cuda_fp16.h>
#include <cstdint>
#include <math.h>

#define S_LEN 4096
#define E_DIM 1024
#define D_DIM 1024

typedef __half h16;

// ---------------- scratch (device globals; no allocation allowed) ----------
__device__ h16   g_xh[(size_t)S_LEN * E_DIM];
__device__ h16   g_xl[(size_t)S_LEN * E_DIM];
__device__ h16   g_Wqh[(size_t)E_DIM * D_DIM];      // Wq split (row-major, no transpose)
__device__ h16   g_Wql[(size_t)E_DIM * D_DIM];
__device__ h16   g_Wkh[(size_t)E_DIM * D_DIM];      // Wk split
__device__ h16   g_Wkl[(size_t)E_DIM * D_DIM];
__device__ h16   g_Wvth[(size_t)D_DIM * E_DIM];     // Wv^T hi only
__device__ h16   g_Mth[(size_t)E_DIM * E_DIM];      // (Wq Wk^T)^T split
__device__ h16   g_Mtl[(size_t)E_DIM * E_DIM];
__device__ h16   g_Th[(size_t)S_LEN * E_DIM];       // T = x M, split
__device__ h16   g_Tl[(size_t)S_LEN * E_DIM];
__device__ h16   g_Vth[(size_t)D_DIM * S_LEN];      // V^T fp16
__device__ float g_Pf[(size_t)S_LEN * S_LEN];       // raw scores (lower tri)
__device__ h16   g_Ph[(size_t)S_LEN * S_LEN];       // unnormalized exp fp16
__device__ int   g_rowmax[S_LEN];
__device__ float g_rowsum[S_LEN];

// ---------------- PTX helpers (sm_80-compatible only) -----------------------
__device__ __forceinline__ uint32_t smem_u32(const void* p) {
    uint32_t a;
    asm("{ .reg .u64 t; cvta.to.shared.u64 t, %1; cvt.u32.u64 %0, t; }" : "=r"(a) : "l"(p));
    return a;
}

#define CP_ASYNC16(saddr, gaddr) \
    asm volatile("cp.async.cg.shared.global [%0], [%1], 16;" \
                 :: "r"(saddr), "l"(gaddr) : "memory")
#define CP_COMMIT() asm volatile("cp.async.commit_group;" ::: "memory")
#define CP_WAIT(N)  asm volatile("cp.async.wait_group %0;" :: "n"(N) : "memory")

#define LDSM4(r0, r1, r2, r3, addr) \
    asm volatile("ldmatrix.sync.aligned.m8n8.x4.shared.b16 {%0,%1,%2,%3}, [%4];" \
                 : "=r"(r0), "=r"(r1), "=r"(r2), "=r"(r3) : "r"(addr))

#define MMA16816(c0, c1, c2, c3, a0, a1, a2, a3, b0, b1) \
    asm volatile("mma.sync.aligned.m16n8k16.row.col.f32.f16.f16.f32 " \
                 "{%0,%1,%2,%3}, {%4,%5,%6,%7}, {%8,%9}, {%0,%1,%2,%3};" \
                 : "+f"(c0), "+f"(c1), "+f"(c2), "+f"(c3) \
                 : "r"(a0), "r"(a1), "r"(a2), "r"(a3), "r"(b0), "r"(b1))

// monotone int encoding of fp32 for atomicMax
__device__ __forceinline__ int encf(float x) {
    int i = __float_as_int(x);
    return (i >= 0) ? i : (i ^ 0x7FFFFFFF);
}
__device__ __forceinline__ float decf(int i) {
    return __int_as_float((i >= 0) ? i : (i ^ 0x7FFFFFFF));
}

// ---------------- aux kernels -----------------------------------------------
// split x, Wq, Wk elementwise; re-init rowmax.
__global__ __launch_bounds__(256)
void split3(const float* __restrict__ x, const float* __restrict__ Wq,
            const float* __restrict__ Wk)
{
    const int g = blockIdx.x * 256 + threadIdx.x;
    const int stride = gridDim.x * 256;
    if (g < S_LEN) g_rowmax[g] = 0x80000000;
    const int NX = S_LEN * E_DIM, NW = E_DIM * D_DIM;
    for (int i = g; i < NX; i += stride) {
        float v = x[i];
        h16 a = __float2half_rn(v);
        g_xh[i] = a;
        g_xl[i] = __float2half_rn(v - __half2float(a));
    }
    for (int i = g; i < NW; i += stride) {
        float v = Wq[i];
        h16 a = __float2half_rn(v);
        g_Wqh[i] = a;
        g_Wql[i] = __float2half_rn(v - __half2float(a));
    }
    for (int i = g; i < NW; i += stride) {
        float v = Wk[i];
        h16 a = __float2half_rn(v);
        g_Wkh[i] = a;
        g_Wkl[i] = __float2half_rn(v - __half2float(a));
    }
}

// Wv^T (hi only): Wvt[d][e] = Wv[e][d]
__global__ __launch_bounds__(256)
void transpose_wv(const float* __restrict__ Wv)
{
    __shared__ float t[32][33];
    const int bx = blockIdx.x * 32;   // d
    const int by = blockIdx.y * 32;   // e
    const int tx = threadIdx.x & 31, ty = threadIdx.x >> 5;
#pragma unroll
    for (int j = ty; j < 32; j += 8)
        t[j][tx] = Wv[(size_t)(by + j) * D_DIM + bx + tx];
    __syncthreads();
#pragma unroll
    for (int j = ty; j < 32; j += 8)
        g_Wvth[(size_t)(bx + j) * E_DIM + by + tx] = __float2half_rn(t[tx][j]);
}

// single-pass softmax: Ph = exp(Pf - rowmax) (unnormalized), rowsum out.
__global__ __launch_bounds__(256)
void softmax_onepass(const float* __restrict__ Pf, h16* __restrict__ Ph)
{
    const int row = blockIdx.x;
    const float* p = Pf + (size_t)row * S_LEN;
    h16* ph = Ph + (size_t)row * S_LEN;
    const int len = row + 1;
    const int tid = threadIdx.x, lane = tid & 31, warp = tid >> 5;
    __shared__ float red[8];

    const float m = decf(g_rowmax[row]);

    float s = 0.0f;
    for (int j = tid; j < len; j += 256) {
        float e = expf(p[j] - m);
        ph[j] = __float2half_rn(e);
        s += e;
    }
#pragma unroll
    for (int o = 16; o; o >>= 1) s += __shfl_xor_sync(0xffffffffu, s, o);
    if (lane == 0) red[warp] = s;
    __syncthreads();
    if (tid == 0) {
        float v = 0.0f;
#pragma unroll
        for (int i = 0; i < 8; i++) v += red[i];
        g_rowsum[row] = v;
    }
    const int kpad = ((row >> 7) + 1) << 7;
    const h16 z = __float2half_rn(0.0f);
    for (int j = len + tid; j < kpad; j += 256) ph[j] = z;
}

// ---------------- GEMM core (compile-time NPROD) -----------------------------
#define RSB     80                   // smem row stride bytes (64B data + 16B pad)
#define TILE_B  (128 * RSB)          // 10240
#define SMEM3   (2 * 4 * TILE_B + 128)   // 82048
#define SMEM1   (2 * 2 * TILE_B + 128)   // 41088

template <int NPROD>
__device__ __forceinline__ void gemm_core(
    uint32_t tiles, const h16* __restrict__ A0, const h16* __restrict__ A1,
    const h16* __restrict__ B0, const h16* __restrict__ B1,
    int Ktot, int NC, float (&acc)[4][4][4])
{
    constexpr int NTILES = (NPROD == 3) ? 4 : 2;
    constexpr uint32_t STAGE_B = NTILES * TILE_B;

    const int tid = threadIdx.x;
    const int wid = tid >> 5;
    const int lane = tid & 31;
    const int wm = wid >> 2;
    const int wn = wid & 3;

#pragma unroll
    for (int i = 0; i < 4; i++)
#pragma unroll
        for (int j = 0; j < 4; j++)
#pragma unroll
            for (int k = 0; k < 4; k++) acc[i][j][k] = 0.0f;

    auto load_stage = [&](int c) {
        const uint32_t st = tiles + (uint32_t)(c & 1) * STAGE_B;
        const int k0 = c * 32;
        const h16* srcs[NTILES];
        if (NPROD == 3) {
            srcs[0] = A0 + k0; srcs[1] = A1 + k0;
            srcs[2] = B0 + k0; srcs[3] = B1 + k0;
        } else {
            srcs[0] = A0 + k0; srcs[1] = B0 + k0;
        }
#pragma unroll
        for (int t = 0; t < NTILES; t++) {
#pragma unroll
            for (int j2 = 0; j2 < 2; j2++) {
                int j = tid + j2 * 256;
                int row = j >> 2, ck = j & 3;
                const void* g = srcs[t] + (size_t)row * Ktot + ck * 8;
                uint32_t s = st + (uint32_t)t * TILE_B + row * RSB + ck * 16;
                CP_ASYNC16(s, g);
            }
        }
        CP_COMMIT();
    };

    load_stage(0);

    const int lr15 = lane & 15;
    const int lhi16 = (lane >> 4) * 16;
    const int l7 = lane & 7;
    const int bmat = lane >> 3;
    const int bnsub = (bmat >> 1) * 8;
    const int bkb = (bmat & 1) * 16;

    for (int c = 0; c < NC; c++) {
        if (c + 1 < NC) { load_stage(c + 1); CP_WAIT(1); }
        else            { CP_WAIT(0); }
        __syncthreads();

        const uint32_t st = tiles + (uint32_t)(c & 1) * STAGE_B;
        const uint32_t aHb = st + (uint32_t)(wm * 64) * RSB;
        const uint32_t aLb = aHb + TILE_B;
        const uint32_t bHb = st + (uint32_t)(NTILES / 2) * TILE_B
                                + (uint32_t)(wn * 32) * RSB;
        const uint32_t bLb = bHb + TILE_B;

#pragma unroll
        for (int ks = 0; ks < 2; ks++) {
            const uint32_t akb  = (uint32_t)(ks * 32 + lhi16);
            const uint32_t bkb2 = (uint32_t)(ks * 32) + bkb;

            uint32_t ah[4][4], al[4][4], bh[2][4], bl[2][4];
#pragma unroll
            for (int mi = 0; mi < 4; mi++) {
                uint32_t ra = (uint32_t)(mi * 16 + lr15) * RSB + akb;
                LDSM4(ah[mi][0], ah[mi][1], ah[mi][2], ah[mi][3], aHb + ra);
                if (NPROD == 3)
                    LDSM4(al[mi][0], al[mi][1], al[mi][2], al[mi][3], aLb + ra);
            }
#pragma unroll
            for (int pi = 0; pi < 2; pi++) {
                uint32_t rb = (uint32_t)(pi * 16 + bnsub + l7) * RSB + bkb2;
                LDSM4(bh[pi][0], bh[pi][1], bh[pi][2], bh[pi][3], bHb + rb);
                if (NPROD == 3)
                    LDSM4(bl[pi][0], bl[pi][1], bl[pi][2], bl[pi][3], bLb + rb);
            }
#pragma unroll
            for (int mi = 0; mi < 4; mi++) {
#pragma unroll
                for (int ni = 0; ni < 4; ni++) {
                    const int pi = ni >> 1, j = (ni & 1) * 2;
                    float* a4 = acc[mi][ni];
                    MMA16816(a4[0], a4[1], a4[2], a4[3],
                             ah[mi][0], ah[mi][1], ah[mi][2], ah[mi][3],
                             bh[pi][j], bh[pi][j + 1]);
                    if (NPROD == 3) {
                        MMA16816(a4[0], a4[1], a4[2], a4[3],
                                 ah[mi][0], ah[mi][1], ah[mi][2], ah[mi][3],
                                 bl[pi][j], bl[pi][j + 1]);
                        MMA16816(a4[0], a4[1], a4[2], a4[3],
                                 al[mi][0], al[mi][1], al[mi][2], al[mi][3],
                                 bh[pi][j], bh[pi][j + 1]);
                    }
                }
            }
        }
        __syncthreads();
    }
}

// split-fp16 epilogue writer (128x128 tile at (m0,n0), ldc)
__device__ __forceinline__ void store_split(
    float (&acc)[4][4][4], h16* __restrict__ oh, h16* __restrict__ ol,
    int m0, int n0, int ldc)
{
    const int lane = threadIdx.x & 31;
    const int wm = (threadIdx.x >> 5) >> 2, wn = (threadIdx.x >> 5) & 3;
    const int gr = lane >> 2, gc = (lane & 3) << 1;
#pragma unroll
    for (int mi = 0; mi < 4; mi++) {
#pragma unroll
        for (int ni = 0; ni < 4; ni++) {
            const int rr = m0 + wm * 64 + mi * 16 + gr;
            const int cc = n0 + wn * 32 + ni * 8 + gc;
            float v0 = acc[mi][ni][0], v1 = acc[mi][ni][1];
            float v2 = acc[mi][ni][2], v3 = acc[mi][ni][3];
            h16 h0 = __float2half_rn(v0), h1 = __float2half_rn(v1);
            h16 h2 = __float2half_rn(v2), h3 = __float2half_rn(v3);
            __half2 hi01 = __halves2half2(h0, h1);
            __half2 hi23 = __halves2half2(h2, h3);
            __half2 lo01 = __halves2half2(__float2half_rn(v0 - __half2float(h0)),
                                          __float2half_rn(v1 - __half2float(h1)));
            __half2 lo23 = __halves2half2(__float2half_rn(v2 - __half2float(h2)),
                                          __float2half_rn(v3 - __half2float(h3)));
            *(__half2*)&oh[(size_t)rr * ldc + cc]       = hi01;
            *(__half2*)&ol[(size_t)rr * ldc + cc]       = lo01;
            *(__half2*)&oh[(size_t)(rr + 8) * ldc + cc] = hi23;
            *(__half2*)&ol[(size_t)(rr + 8) * ldc + cc] = lo23;
        }
    }
}

// ---------------- kernels ----------------------------------------------------
// merged: t<64 -> Mt = Wk·Wq^T (3-product, split out); t>=64 -> V^T (1-product)
__global__ __launch_bounds__(256, 2)
void mm_mv()
{
    extern __shared__ char smem[];
    const uint32_t tiles = (smem_u32(smem) + 127u) & ~127u;

    if (blockIdx.x < 64) {
        const int t = blockIdx.x;
        const int m0 = (t >> 3) * 128;   // b (rows of Mt)
        const int n0 = (t & 7) * 128;    // a (cols of Mt)
        float acc[4][4][4];
        gemm_core<3>(tiles,
                     g_Wkh + (size_t)m0 * D_DIM, g_Wkl + (size_t)m0 * D_DIM,
                     g_Wqh + (size_t)n0 * D_DIM, g_Wql + (size_t)n0 * D_DIM,
                     D_DIM, D_DIM / 32, acc);
        store_split(acc, g_Mth, g_Mtl, m0, n0, E_DIM);
    } else {
        const int u = blockIdx.x - 64;
        const int m0 = (u >> 5) * 128;   // d
        const int n0 = (u & 31) * 128;   // s
        float acc[4][4][4];
        gemm_core<1>(tiles,
                     g_Wvth + (size_t)m0 * E_DIM, nullptr,
                     g_xh + (size_t)n0 * E_DIM, nullptr,
                     E_DIM, E_DIM / 32, acc);
        const int lane = threadIdx.x & 31;
        const int wm = (threadIdx.x >> 5) >> 2, wn = (threadIdx.x >> 5) & 3;
        const int gr = lane >> 2, gc = (lane & 3) << 1;
#pragma unroll
        for (int mi = 0; mi < 4; mi++) {
#pragma unroll
            for (int ni = 0; ni < 4; ni++) {
                const int rr = m0 + wm * 64 + mi * 16 + gr;
                const int cc = n0 + wn * 32 + ni * 8 + gc;
                __half2 a = __halves2half2(__float2half_rn(acc[mi][ni][0]),
                                           __float2half_rn(acc[mi][ni][1]));
                __half2 b = __halves2half2(__float2half_rn(acc[mi][ni][2]),
                                           __float2half_rn(acc[mi][ni][3]));
                *(__half2*)&g_Vth[(size_t)rr * S_LEN + cc]       = a;
                *(__half2*)&g_Vth[(size_t)(rr + 8) * S_LEN + cc] = b;
            }
        }
    }
}

// T = x · M  (A = x split, B = Mt split), split output
__global__ __launch_bounds__(256, 2)
void mm_t()
{
    extern __shared__ char smem[];
    const uint32_t tiles = (smem_u32(smem) + 127u) & ~127u;
    const int t = blockIdx.x;
    const int m0 = (t >> 3) * 128;   // s
    const int n0 = (t & 7) * 128;    // b
    float acc[4][4][4];
    gemm_core<3>(tiles,
                 g_xh + (size_t)m0 * E_DIM, g_xl + (size_t)m0 * E_DIM,
                 g_Mth + (size_t)n0 * E_DIM, g_Mtl + (size_t)n0 * E_DIM,
                 E_DIM, E_DIM / 32, acc);
    store_split(acc, g_Th, g_Tl, m0, n0, E_DIM);
}

// causal scores = T · x^T (3-product), Pf + rowmax atomics
__global__ __launch_bounds__(256, 2)
void mm_scores()
{
    extern __shared__ char smem[];
    const uint32_t tiles = (smem_u32(smem) + 127u) & ~127u;
    int t = blockIdx.x;
    int br = (int)((sqrtf(8.0f * (float)t + 1.0f) - 1.0f) * 0.5f);
    while ((br + 1) * (br + 2) / 2 <= t) br++;
    while (br * (br + 1) / 2 > t) br--;
    const int bc = t - br * (br + 1) / 2;
    const int m0 = br * 128, n0 = bc * 128;

    float acc[4][4][4];
    gemm_core<3>(tiles,
                 g_Th + (size_t)m0 * E_DIM, g_Tl + (size_t)m0 * E_DIM,
                 g_xh + (size_t)n0 * E_DIM, g_xl + (size_t)n0 * E_DIM,
                 E_DIM, E_DIM / 32, acc);

    const int lane = threadIdx.x & 31;
    const int wm = (threadIdx.x >> 5) >> 2, wn = (threadIdx.x >> 5) & 3;
    const int gr = lane >> 2, gc = (lane & 3) << 1;
    const bool diag = (bc == br);
    const float scale = 1.0f / 32.0f;
#pragma unroll
    for (int mi = 0; mi < 4; mi++) {
        const int r0 = m0 + wm * 64 + mi * 16 + gr;
        const int r1 = r0 + 8;
        float mx0 = -3.4e38f, mx1 = -3.4e38f;
#pragma unroll
        for (int ni = 0; ni < 4; ni++) {
            const int cc = n0 + wn * 32 + ni * 8 + gc;
            float v0 = acc[mi][ni][0] * scale;
            float v1 = acc[mi][ni][1] * scale;
            float v2 = acc[mi][ni][2] * scale;
            float v3 = acc[mi][ni][3] * scale;
            *(float2*)&g_Pf[(size_t)r0 * S_LEN + cc] = make_float2(v0, v1);
            *(float2*)&g_Pf[(size_t)r1 * S_LEN + cc] = make_float2(v2, v3);
            if (!diag || cc     <= r0) mx0 = fmaxf(mx0, v0);
            if (!diag || cc + 1 <= r0) mx0 = fmaxf(mx0, v1);
            if (!diag || cc     <= r1) mx1 = fmaxf(mx1, v2);
            if (!diag || cc + 1 <= r1) mx1 = fmaxf(mx1, v3);
        }
        mx0 = fmaxf(mx0, __shfl_xor_sync(0xffffffffu, mx0, 1));
        mx0 = fmaxf(mx0, __shfl_xor_sync(0xffffffffu, mx0, 2));
        mx1 = fmaxf(mx1, __shfl_xor_sync(0xffffffffu, mx1, 1));
        mx1 = fmaxf(mx1, __shfl_xor_sync(0xffffffffu, mx1, 2));
        if ((lane & 3) == 0) {
            atomicMax(&g_rowmax[r0], encf(mx0));
            atomicMax(&g_rowmax[r1], encf(mx1));
        }
    }
}

// PV: causal, heavy-first zigzag; epilogue scales by 1/rowsum.
__global__ __launch_bounds__(256, 2)
void mm_pv(float* __restrict__ out)
{
    extern __shared__ char smem[];
    const uint32_t tiles = (smem_u32(smem) + 127u) & ~127u;
    const int t = blockIdx.x;
    const int r = (t < 148) ? t : (403 - t);
    const int br = 31 - (r >> 3);
    const int bc = r & 7;
    const int m0 = br * 128, n0 = bc * 128;
    const int NC = (br + 1) * 4;

    float acc[4][4][4];
    gemm_core<1>(tiles,
                 g_Ph + (size_t)m0 * S_LEN, nullptr,
                 g_Vth + (size_t)n0 * S_LEN, nullptr,
                 S_LEN, NC, acc);

    const int lane = threadIdx.x & 31;
    const int wm = (threadIdx.x >> 5) >> 2, wn = (threadIdx.x >> 5) & 3;
    const int gr = lane >> 2, gc = (lane & 3) << 1;
#pragma unroll
    for (int mi = 0; mi < 4; mi++) {
        const int r0 = m0 + wm * 64 + mi * 16 + gr;
        const float inv0 = 1.0f / g_rowsum[r0];
        const float inv1 = 1.0f / g_rowsum[r0 + 8];
#pragma unroll
        for (int ni = 0; ni < 4; ni++) {
            const int cc = n0 + wn * 32 + ni * 8 + gc;
            *(float2*)&out[(size_t)r0 * D_DIM + cc] =
                make_float2(acc[mi][ni][0] * inv0, acc[mi][ni][1] * inv0);
            *(float2*)&out[(size_t)(r0 + 8) * D_DIM + cc] =
                make_float2(acc[mi][ni][2] * inv1, acc[mi][ni][3] * inv1);
        }
    }
}

// ---------------- host launcher ---------------------------------------------
extern "C" void kernel_launch(void* const* d_in, const int* in_sizes, int n_in,
                              void* d_out, int out_size)
{
    const float* x  = (const float*)d_in[0];
    const float* Wq = (const float*)d_in[1];
    const float* Wk = (const float*)d_in[2];
    const float* Wv = (const float*)d_in[3];
    float* out = (float*)d_out;

    float *Pf;
    h16 *Ph;
    cudaGetSymbolAddress((void**)&Pf, g_Pf);
    cudaGetSymbolAddress((void**)&Ph, g_Ph);

    cudaFuncSetAttribute(mm_mv,     cudaFuncAttributeMaxDynamicSharedMemorySize, SMEM3);
    cudaFuncSetAttribute(mm_t,      cudaFuncAttributeMaxDynamicSharedMemorySize, SMEM3);
    cudaFuncSetAttribute(mm_scores, cudaFuncAttributeMaxDynamicSharedMemorySize, SMEM3);
    cudaFuncSetAttribute(mm_pv,     cudaFuncAttributeMaxDynamicSharedMemorySize, SMEM1);

    // 1) split x, Wq, Wk (+ rowmax re-init)
    split3<<<2048, 256>>>(x, Wq, Wk);
    // 2) Wv^T (hi only)
    transpose_wv<<<dim3(32, 32), 256>>>(Wv);
    // 3) merged: Mt = Wk Wq^T (heavy, first) + V^T projection (light, tail)
    mm_mv<<<320, 256, SMEM3>>>();
    // 4) T = x · M (split out)
    mm_t<<<256, 256, SMEM3>>>();
    // 5) causal scores = T · x^T (+ rowmax)
    mm_scores<<<528, 256, SMEM3>>>();
    // 6) single-pass softmax
    softmax_onepass<<<S_LEN, 256>>>(Pf, Ph);
    // 7) out = (P @ V) / rowsum
    mm_pv<<<256, 256, SMEM1>>>(out);
}

// round 10
// speedup vs baseline: 1.3956x; 1.0225x over previous
#include <cuda_runtime.h>
#include <cuda_fp16.h>
#include <cstdint>
#include <math.h>

#define S_LEN 4096
#define E_DIM 1024
#define D_DIM 1024

typedef __half h16;

// ---------------- scratch (device globals; no allocation allowed) ----------
__device__ h16   g_xh[(size_t)S_LEN * E_DIM];
__device__ h16   g_xl[(size_t)S_LEN * E_DIM];
__device__ h16   g_Wqh[(size_t)E_DIM * D_DIM];      // Wq split (row-major)
__device__ h16   g_Wql[(size_t)E_DIM * D_DIM];
__device__ h16   g_Wkh[(size_t)E_DIM * D_DIM];      // Wk split
__device__ h16   g_Wkl[(size_t)E_DIM * D_DIM];
__device__ h16   g_Wvth[(size_t)D_DIM * E_DIM];     // Wv^T hi only
__device__ h16   g_Mth[(size_t)E_DIM * E_DIM];      // (Wq Wk^T)^T split
__device__ h16   g_Mtl[(size_t)E_DIM * E_DIM];
__device__ h16   g_Th[(size_t)S_LEN * E_DIM];       // T = x M, split
__device__ h16   g_Tl[(size_t)S_LEN * E_DIM];
__device__ h16   g_Vth[(size_t)D_DIM * S_LEN];      // V^T fp16
__device__ float g_Pf[(size_t)S_LEN * S_LEN];       // raw scores (lower tri)
__device__ h16   g_Ph[(size_t)S_LEN * S_LEN];       // unnormalized exp fp16
__device__ int   g_rowmax[S_LEN];
__device__ float g_rowsum[S_LEN];

// ---------------- PTX helpers (sm_80-compatible only) -----------------------
__device__ __forceinline__ uint32_t smem_u32(const void* p) {
    uint32_t a;
    asm("{ .reg .u64 t; cvta.to.shared.u64 t, %1; cvt.u32.u64 %0, t; }" : "=r"(a) : "l"(p));
    return a;
}

#define CP_ASYNC16(saddr, gaddr) \
    asm volatile("cp.async.cg.shared.global [%0], [%1], 16;" \
                 :: "r"(saddr), "l"(gaddr) : "memory")
#define CP_COMMIT() asm volatile("cp.async.commit_group;" ::: "memory")
#define CP_WAIT(N)  asm volatile("cp.async.wait_group %0;" :: "n"(N) : "memory")

#define LDSM4(r0, r1, r2, r3, addr) \
    asm volatile("ldmatrix.sync.aligned.m8n8.x4.shared.b16 {%0,%1,%2,%3}, [%4];" \
                 : "=r"(r0), "=r"(r1), "=r"(r2), "=r"(r3) : "r"(addr))

#define MMA16816(c0, c1, c2, c3, a0, a1, a2, a3, b0, b1) \
    asm volatile("mma.sync.aligned.m16n8k16.row.col.f32.f16.f16.f32 " \
                 "{%0,%1,%2,%3}, {%4,%5,%6,%7}, {%8,%9}, {%0,%1,%2,%3};" \
                 : "+f"(c0), "+f"(c1), "+f"(c2), "+f"(c3) \
                 : "r"(a0), "r"(a1), "r"(a2), "r"(a3), "r"(b0), "r"(b1))

// monotone int encoding of fp32 for atomicMax
__device__ __forceinline__ int encf(float x) {
    int i = __float_as_int(x);
    return (i >= 0) ? i : (i ^ 0x7FFFFFFF);
}
__device__ __forceinline__ float decf(int i) {
    return __int_as_float((i >= 0) ? i : (i ^ 0x7FFFFFFF));
}

// ---------------- prep: Wv^T tiles + elementwise splits, one launch ---------
// blocks [0,1024): Wv transpose tiles; blocks [1024,3072): strided splits.
__global__ __launch_bounds__(256)
void prep(const float* __restrict__ x, const float* __restrict__ Wq,
          const float* __restrict__ Wk, const float* __restrict__ Wv)
{
    __shared__ float t[32][33];
    if (blockIdx.x < 1024) {
        const int u = blockIdx.x;
        const int bx = (u & 31) * 32;   // d
        const int by = (u >> 5) * 32;   // e
        const int tx = threadIdx.x & 31, ty = threadIdx.x >> 5;
#pragma unroll
        for (int j = ty; j < 32; j += 8)
            t[j][tx] = Wv[(size_t)(by + j) * D_DIM + bx + tx];
        __syncthreads();
#pragma unroll
        for (int j = ty; j < 32; j += 8)
            g_Wvth[(size_t)(bx + j) * E_DIM + by + tx] = __float2half_rn(t[tx][j]);
        return;
    }
    const int g = (blockIdx.x - 1024) * 256 + threadIdx.x;
    const int stride = 2048 * 256;
    if (g < S_LEN) g_rowmax[g] = 0x80000000;
    const int NX = S_LEN * E_DIM, NW = E_DIM * D_DIM;
    for (int i = g; i < NX; i += stride) {
        float v = x[i];
        h16 a = __float2half_rn(v);
        g_xh[i] = a;
        g_xl[i] = __float2half_rn(v - __half2float(a));
    }
    for (int i = g; i < NW; i += stride) {
        float v = Wq[i];
        h16 a = __float2half_rn(v);
        g_Wqh[i] = a;
        g_Wql[i] = __float2half_rn(v - __half2float(a));
    }
    for (int i = g; i < NW; i += stride) {
        float v = Wk[i];
        h16 a = __float2half_rn(v);
        g_Wkh[i] = a;
        g_Wkl[i] = __float2half_rn(v - __half2float(a));
    }
}

// single-pass softmax: Ph = exp(Pf - rowmax) (unnormalized), rowsum out.
__global__ __launch_bounds__(256)
void softmax_onepass(const float* __restrict__ Pf, h16* __restrict__ Ph)
{
    const int row = blockIdx.x;
    const float* p = Pf + (size_t)row * S_LEN;
    h16* ph = Ph + (size_t)row * S_LEN;
    const int len = row + 1;
    const int tid = threadIdx.x, lane = tid & 31, warp = tid >> 5;
    __shared__ float red[8];

    const float m = decf(g_rowmax[row]);

    float s = 0.0f;
    for (int j = tid; j < len; j += 256) {
        float e = expf(p[j] - m);
        ph[j] = __float2half_rn(e);
        s += e;
    }
#pragma unroll
    for (int o = 16; o; o >>= 1) s += __shfl_xor_sync(0xffffffffu, s, o);
    if (lane == 0) red[warp] = s;
    __syncthreads();
    if (tid == 0) {
        float v = 0.0f;
#pragma unroll
        for (int i = 0; i < 8; i++) v += red[i];
        g_rowsum[row] = v;
    }
    const int kpad = ((row >> 7) + 1) << 7;
    const h16 z = __float2half_rn(0.0f);
    for (int j = len + tid; j < kpad; j += 256) ph[j] = z;
}

// ---------------- GEMM core (compile-time NPROD) -----------------------------
// Single barrier per K-chunk: CP_WAIT(0) + __syncthreads() orders BOTH the
// arrival of stage c's data AND last iteration's LDSM reads of stage (c+1)&1
// before the new cp.async writes into it. Product-major MMA ordering spreads
// accumulator RAW chains 16 independent MMAs apart.
#define RSB     80                   // smem row stride bytes (64B data + 16B pad)
#define TILE_B  (128 * RSB)          // 10240
#define SMEM3   (2 * 4 * TILE_B + 128)   // 82048
#define SMEM1   (2 * 2 * TILE_B + 128)   // 41088

template <int NPROD>
__device__ __forceinline__ void gemm_core(
    uint32_t tiles, const h16* __restrict__ A0, const h16* __restrict__ A1,
    const h16* __restrict__ B0, const h16* __restrict__ B1,
    int Ktot, int NC, float (&acc)[4][4][4])
{
    constexpr int NTILES = (NPROD == 3) ? 4 : 2;
    constexpr uint32_t STAGE_B = NTILES * TILE_B;

    const int tid = threadIdx.x;
    const int wid = tid >> 5;
    const int lane = tid & 31;
    const int wm = wid >> 2;
    const int wn = wid & 3;

#pragma unroll
    for (int i = 0; i < 4; i++)
#pragma unroll
        for (int j = 0; j < 4; j++)
#pragma unroll
            for (int k = 0; k < 4; k++) acc[i][j][k] = 0.0f;

    auto load_stage = [&](int c) {
        const uint32_t st = tiles + (uint32_t)(c & 1) * STAGE_B;
        const int k0 = c * 32;
        const h16* srcs[NTILES];
        if (NPROD == 3) {
            srcs[0] = A0 + k0; srcs[1] = A1 + k0;
            srcs[2] = B0 + k0; srcs[3] = B1 + k0;
        } else {
            srcs[0] = A0 + k0; srcs[1] = B0 + k0;
        }
#pragma unroll
        for (int t = 0; t < NTILES; t++) {
#pragma unroll
            for (int j2 = 0; j2 < 2; j2++) {
                int j = tid + j2 * 256;
                int row = j >> 2, ck = j & 3;
                const void* g = srcs[t] + (size_t)row * Ktot + ck * 8;
                uint32_t s = st + (uint32_t)t * TILE_B + row * RSB + ck * 16;
                CP_ASYNC16(s, g);
            }
        }
        CP_COMMIT();
    };

    load_stage(0);

    const int lr15 = lane & 15;
    const int lhi16 = (lane >> 4) * 16;
    const int l7 = lane & 7;
    const int bmat = lane >> 3;
    const int bnsub = (bmat >> 1) * 8;
    const int bkb = (bmat & 1) * 16;

    for (int c = 0; c < NC; c++) {
        CP_WAIT(0);
        __syncthreads();
        if (c + 1 < NC) load_stage(c + 1);

        const uint32_t st = tiles + (uint32_t)(c & 1) * STAGE_B;
        const uint32_t aHb = st + (uint32_t)(wm * 64) * RSB;
        const uint32_t aLb = aHb + TILE_B;
        const uint32_t bHb = st + (uint32_t)(NTILES / 2) * TILE_B
                                + (uint32_t)(wn * 32) * RSB;
        const uint32_t bLb = bHb + TILE_B;

#pragma unroll
        for (int ks = 0; ks < 2; ks++) {
            const uint32_t akb  = (uint32_t)(ks * 32 + lhi16);
            const uint32_t bkb2 = (uint32_t)(ks * 32) + bkb;

            uint32_t ah[4][4], al[4][4], bh[2][4], bl[2][4];
#pragma unroll
            for (int mi = 0; mi < 4; mi++) {
                uint32_t ra = (uint32_t)(mi * 16 + lr15) * RSB + akb;
                LDSM4(ah[mi][0], ah[mi][1], ah[mi][2], ah[mi][3], aHb + ra);
                if (NPROD == 3)
                    LDSM4(al[mi][0], al[mi][1], al[mi][2], al[mi][3], aLb + ra);
            }
#pragma unroll
            for (int pi = 0; pi < 2; pi++) {
                uint32_t rb = (uint32_t)(pi * 16 + bnsub + l7) * RSB + bkb2;
                LDSM4(bh[pi][0], bh[pi][1], bh[pi][2], bh[pi][3], bHb + rb);
                if (NPROD == 3)
                    LDSM4(bl[pi][0], bl[pi][1], bl[pi][2], bl[pi][3], bLb + rb);
            }
            // product-major: hh over all 16 accs, then hl, then lh
#pragma unroll
            for (int mi = 0; mi < 4; mi++)
#pragma unroll
                for (int ni = 0; ni < 4; ni++) {
                    const int pi = ni >> 1, j = (ni & 1) * 2;
                    float* a4 = acc[mi][ni];
                    MMA16816(a4[0], a4[1], a4[2], a4[3],
                             ah[mi][0], ah[mi][1], ah[mi][2], ah[mi][3],
                             bh[pi][j], bh[pi][j + 1]);
                }
            if (NPROD == 3) {
#pragma unroll
                for (int mi = 0; mi < 4; mi++)
#pragma unroll
                    for (int ni = 0; ni < 4; ni++) {
                        const int pi = ni >> 1, j = (ni & 1) * 2;
                        float* a4 = acc[mi][ni];
                        MMA16816(a4[0], a4[1], a4[2], a4[3],
                                 ah[mi][0], ah[mi][1], ah[mi][2], ah[mi][3],
                                 bl[pi][j], bl[pi][j + 1]);
                    }
#pragma unroll
                for (int mi = 0; mi < 4; mi++)
#pragma unroll
                    for (int ni = 0; ni < 4; ni++) {
                        const int pi = ni >> 1, j = (ni & 1) * 2;
                        float* a4 = acc[mi][ni];
                        MMA16816(a4[0], a4[1], a4[2], a4[3],
                                 al[mi][0], al[mi][1], al[mi][2], al[mi][3],
                                 bh[pi][j], bh[pi][j + 1]);
                    }
            }
        }
    }
}

// split-fp16 epilogue writer (128x128 tile at (m0,n0), ldc)
__device__ __forceinline__ void store_split(
    float (&acc)[4][4][4], h16* __restrict__ oh, h16* __restrict__ ol,
    int m0, int n0, int ldc)
{
    const int lane = threadIdx.x & 31;
    const int wm = (threadIdx.x >> 5) >> 2, wn = (threadIdx.x >> 5) & 3;
    const int gr = lane >> 2, gc = (lane & 3) << 1;
#pragma unroll
    for (int mi = 0; mi < 4; mi++) {
#pragma unroll
        for (int ni = 0; ni < 4; ni++) {
            const int rr = m0 + wm * 64 + mi * 16 + gr;
            const int cc = n0 + wn * 32 + ni * 8 + gc;
            float v0 = acc[mi][ni][0], v1 = acc[mi][ni][1];
            float v2 = acc[mi][ni][2], v3 = acc[mi][ni][3];
            h16 h0 = __float2half_rn(v0), h1 = __float2half_rn(v1);
            h16 h2 = __float2half_rn(v2), h3 = __float2half_rn(v3);
            __half2 hi01 = __halves2half2(h0, h1);
            __half2 hi23 = __halves2half2(h2, h3);
            __half2 lo01 = __halves2half2(__float2half_rn(v0 - __half2float(h0)),
                                          __float2half_rn(v1 - __half2float(h1)));
            __half2 lo23 = __halves2half2(__float2half_rn(v2 - __half2float(h2)),
                                          __float2half_rn(v3 - __half2float(h3)));
            *(__half2*)&oh[(size_t)rr * ldc + cc]       = hi01;
            *(__half2*)&ol[(size_t)rr * ldc + cc]       = lo01;
            *(__half2*)&oh[(size_t)(rr + 8) * ldc + cc] = hi23;
            *(__half2*)&ol[(size_t)(rr + 8) * ldc + cc] = lo23;
        }
    }
}

// ---------------- kernels ----------------------------------------------------
// merged: t<64 -> Mt = Wk·Wq^T (3-product, split out); t>=64 -> V^T (1-product)
__global__ __launch_bounds__(256, 2)
void mm_mv()
{
    extern __shared__ char smem[];
    const uint32_t tiles = (smem_u32(smem) + 127u) & ~127u;

    if (blockIdx.x < 64) {
        const int t = blockIdx.x;
        const int m0 = (t >> 3) * 128;
        const int n0 = (t & 7) * 128;
        float acc[4][4][4];
        gemm_core<3>(tiles,
                     g_Wkh + (size_t)m0 * D_DIM, g_Wkl + (size_t)m0 * D_DIM,
                     g_Wqh + (size_t)n0 * D_DIM, g_Wql + (size_t)n0 * D_DIM,
                     D_DIM, D_DIM / 32, acc);
        store_split(acc, g_Mth, g_Mtl, m0, n0, E_DIM);
    } else {
        const int u = blockIdx.x - 64;
        const int m0 = (u >> 5) * 128;   // d
        const int n0 = (u & 31) * 128;   // s
        float acc[4][4][4];
        gemm_core<1>(tiles,
                     g_Wvth + (size_t)m0 * E_DIM, nullptr,
                     g_xh + (size_t)n0 * E_DIM, nullptr,
                     E_DIM, E_DIM / 32, acc);
        const int lane = threadIdx.x & 31;
        const int wm = (threadIdx.x >> 5) >> 2, wn = (threadIdx.x >> 5) & 3;
        const int gr = lane >> 2, gc = (lane & 3) << 1;
#pragma unroll
        for (int mi = 0; mi < 4; mi++) {
#pragma unroll
            for (int ni = 0; ni < 4; ni++) {
                const int rr = m0 + wm * 64 + mi * 16 + gr;
                const int cc = n0 + wn * 32 + ni * 8 + gc;
                __half2 a = __halves2half2(__float2half_rn(acc[mi][ni][0]),
                                           __float2half_rn(acc[mi][ni][1]));
                __half2 b = __halves2half2(__float2half_rn(acc[mi][ni][2]),
                                           __float2half_rn(acc[mi][ni][3]));
                *(__half2*)&g_Vth[(size_t)rr * S_LEN + cc]       = a;
                *(__half2*)&g_Vth[(size_t)(rr + 8) * S_LEN + cc] = b;
            }
        }
    }
}

// T = x · M  (A = x split, B = Mt split), split output
__global__ __launch_bounds__(256, 2)
void mm_t()
{
    extern __shared__ char smem[];
    const uint32_t tiles = (smem_u32(smem) + 127u) & ~127u;
    const int t = blockIdx.x;
    const int m0 = (t >> 3) * 128;   // s
    const int n0 = (t & 7) * 128;    // b
    float acc[4][4][4];
    gemm_core<3>(tiles,
                 g_xh + (size_t)m0 * E_DIM, g_xl + (size_t)m0 * E_DIM,
                 g_Mth + (size_t)n0 * E_DIM, g_Mtl + (size_t)n0 * E_DIM,
                 E_DIM, E_DIM / 32, acc);
    store_split(acc, g_Th, g_Tl, m0, n0, E_DIM);
}

// causal scores = T · x^T (3-product), Pf + rowmax atomics
__global__ __launch_bounds__(256, 2)
void mm_scores()
{
    extern __shared__ char smem[];
    const uint32_t tiles = (smem_u32(smem) + 127u) & ~127u;
    int t = blockIdx.x;
    int br = (int)((sqrtf(8.0f * (float)t + 1.0f) - 1.0f) * 0.5f);
    while ((br + 1) * (br + 2) / 2 <= t) br++;
    while (br * (br + 1) / 2 > t) br--;
    const int bc = t - br * (br + 1) / 2;
    const int m0 = br * 128, n0 = bc * 128;

    float acc[4][4][4];
    gemm_core<3>(tiles,
                 g_Th + (size_t)m0 * E_DIM, g_Tl + (size_t)m0 * E_DIM,
                 g_xh + (size_t)n0 * E_DIM, g_xl + (size_t)n0 * E_DIM,
                 E_DIM, E_DIM / 32, acc);

    const int lane = threadIdx.x & 31;
    const int wm = (threadIdx.x >> 5) >> 2, wn = (threadIdx.x >> 5) & 3;
    const int gr = lane >> 2, gc = (lane & 3) << 1;
    const bool diag = (bc == br);
    const float scale = 1.0f / 32.0f;
#pragma unroll
    for (int mi = 0; mi < 4; mi++) {
        const int r0 = m0 + wm * 64 + mi * 16 + gr;
        const int r1 = r0 + 8;
        float mx0 = -3.4e38f, mx1 = -3.4e38f;
#pragma unroll
        for (int ni = 0; ni < 4; ni++) {
            const int cc = n0 + wn * 32 + ni * 8 + gc;
            float v0 = acc[mi][ni][0] * scale;
            float v1 = acc[mi][ni][1] * scale;
            float v2 = acc[mi][ni][2] * scale;
            float v3 = acc[mi][ni][3] * scale;
            *(float2*)&g_Pf[(size_t)r0 * S_LEN + cc] = make_float2(v0, v1);
            *(float2*)&g_Pf[(size_t)r1 * S_LEN + cc] = make_float2(v2, v3);
            if (!diag || cc     <= r0) mx0 = fmaxf(mx0, v0);
            if (!diag || cc + 1 <= r0) mx0 = fmaxf(mx0, v1);
            if (!diag || cc     <= r1) mx1 = fmaxf(mx1, v2);
            if (!diag || cc + 1 <= r1) mx1 = fmaxf(mx1, v3);
        }
        mx0 = fmaxf(mx0, __shfl_xor_sync(0xffffffffu, mx0, 1));
        mx0 = fmaxf(mx0, __shfl_xor_sync(0xffffffffu, mx0, 2));
        mx1 = fmaxf(mx1, __shfl_xor_sync(0xffffffffu, mx1, 1));
        mx1 = fmaxf(mx1, __shfl_xor_sync(0xffffffffu, mx1, 2));
        if ((lane & 3) == 0) {
            atomicMax(&g_rowmax[r0], encf(mx0));
            atomicMax(&g_rowmax[r1], encf(mx1));
        }
    }
}

// PV: causal, heavy-first zigzag; epilogue scales by 1/rowsum.
__global__ __launch_bounds__(256, 2)
void mm_pv(float* __restrict__ out)
{
    extern __shared__ char smem[];
    const uint32_t tiles = (smem_u32(smem) + 127u) & ~127u;
    const int t = blockIdx.x;
    const int r = (t < 148) ? t : (403 - t);
    const int br = 31 - (r >> 3);
    const int bc = r & 7;
    const int m0 = br * 128, n0 = bc * 128;
    const int NC = (br + 1) * 4;

    float acc[4][4][4];
    gemm_core<1>(tiles,
                 g_Ph + (size_t)m0 * S_LEN, nullptr,
                 g_Vth + (size_t)n0 * S_LEN, nullptr,
                 S_LEN, NC, acc);

    const int lane = threadIdx.x & 31;
    const int wm = (threadIdx.x >> 5) >> 2, wn = (threadIdx.x >> 5) & 3;
    const int gr = lane >> 2, gc = (lane & 3) << 1;
#pragma unroll
    for (int mi = 0; mi < 4; mi++) {
        const int r0 = m0 + wm * 64 + mi * 16 + gr;
        const float inv0 = 1.0f / g_rowsum[r0];
        const float inv1 = 1.0f / g_rowsum[r0 + 8];
#pragma unroll
        for (int ni = 0; ni < 4; ni++) {
            const int cc = n0 + wn * 32 + ni * 8 + gc;
            *(float2*)&out[(size_t)r0 * D_DIM + cc] =
                make_float2(acc[mi][ni][0] * inv0, acc[mi][ni][1] * inv0);
            *(float2*)&out[(size_t)(r0 + 8) * D_DIM + cc] =
                make_float2(acc[mi][ni][2] * inv1, acc[mi][ni][3] * inv1);
        }
    }
}

// ---------------- host launcher ---------------------------------------------
extern "C" void kernel_launch(void* const* d_in, const int* in_sizes, int n_in,
                              void* d_out, int out_size)
{
    const float* x  = (const float*)d_in[0];
    const float* Wq = (const float*)d_in[1];
    const float* Wk = (const float*)d_in[2];
    const float* Wv = (const float*)d_in[3];
    float* out = (float*)d_out;

    float *Pf;
    h16 *Ph;
    cudaGetSymbolAddress((void**)&Pf, g_Pf);
    cudaGetSymbolAddress((void**)&Ph, g_Ph);

    cudaFuncSetAttribute(mm_mv,     cudaFuncAttributeMaxDynamicSharedMemorySize, SMEM3);
    cudaFuncSetAttribute(mm_t,      cudaFuncAttributeMaxDynamicSharedMemorySize, SMEM3);
    cudaFuncSetAttribute(mm_scores, cudaFuncAttributeMaxDynamicSharedMemorySize, SMEM3);
    cudaFuncSetAttribute(mm_pv,     cudaFuncAttributeMaxDynamicSharedMemorySize, SMEM1);

    // 1) prep: Wv^T tiles + splits of x/Wq/Wk + rowmax re-init (one launch)
    prep<<<3072, 256>>>(x, Wq, Wk, Wv);
    // 2) merged: Mt = Wk Wq^T (heavy, first) + V^T projection (light, tail)
    mm_mv<<<320, 256, SMEM3>>>();
    // 3) T = x · M (split out)
    mm_t<<<256, 256, SMEM3>>>();
    // 4) causal scores = T · x^T (+ rowmax)
    mm_scores<<<528, 256, SMEM3>>>();
    // 5) single-pass softmax
    softmax_onepass<<<S_LEN, 256>>>(Pf, Ph);
    // 6) out = (P @ V) / rowsum
    mm_pv<<<256, 256, SMEM1>>>(out);
}